// round 1
// baseline (speedup 1.0000x reference)
#include <cuda_runtime.h>
#include <cuda_bf16.h>
#include <math.h>

#define NN 30000
#define EE 480000
#define ET (EE + NN)          // edges + self loops
#define FIN 4096
#define HC 512                // HEADS*HID
#define HEADS 4
#define HID 128
#define CLS 6

// ---------------- scratch (static device globals; no runtime allocation) ----
__device__ float    g_h1[(size_t)NN * HC];     // x @ W1
__device__ float    g_out1[(size_t)NN * HC];   // layer-1 aggregation
__device__ float    g_as1[NN * HEADS];
__device__ float    g_ad1[NN * HEADS];
__device__ unsigned g_mkey1[NN * HEADS];
__device__ float    g_den1[NN * HEADS];
__device__ float    g_p1[(size_t)ET * HEADS];
__device__ float    g_h2[NN * CLS];
__device__ float    g_as2[NN];
__device__ float    g_ad2[NN];
__device__ unsigned g_mkey2[NN];
__device__ float    g_den2[NN];
__device__ float    g_p2[ET];

// ---- monotone float->uint key for atomic max (sentinel 0 < key(-inf)) ------
__device__ __forceinline__ unsigned fkey(float f) {
    unsigned b = __float_as_uint(f);
    return (b & 0x80000000u) ? ~b : (b | 0x80000000u);
}
__device__ __forceinline__ float funkey(unsigned k) {
    return __uint_as_float((k & 0x80000000u) ? (k & 0x7FFFFFFFu) : ~k);
}
__device__ __forceinline__ float lrelu(float v) { return v > 0.f ? v : 0.2f * v; }

// ---------------- init: zero accumulators, bias-init output -----------------
__global__ void init_kernel(const float* __restrict__ b2, float* __restrict__ out) {
    int i = blockIdx.x * blockDim.x + threadIdx.x;
    if (i < NN * HC)    g_out1[i] = 0.f;
    if (i < NN * HEADS) { g_den1[i] = 0.f; g_mkey1[i] = 0u; }
    if (i < NN)         { g_den2[i] = 0.f; g_mkey2[i] = 0u; }
    if (i < NN * CLS)   out[i] = b2[i % CLS];
}

// ---------------- GEMM1: h1 = x @ W1  (M=30000, K=4096, N=512) --------------
#define BM 128
#define BN 128
#define BK 16
__global__ __launch_bounds__(256, 2) void gemm1_kernel(
    const float* __restrict__ A, const float* __restrict__ B) {
    __shared__ float As[BK][BM + 4];
    __shared__ float Bs[BK][BN];
    const int t  = threadIdx.x;
    const int m0 = blockIdx.y * BM;
    const int n0 = blockIdx.x * BN;
    const int ty = t >> 4;     // 0..15 -> rows ty*8..
    const int tx = t & 15;     // 0..15 -> cols tx*8..

    float acc[8][8];
#pragma unroll
    for (int i = 0; i < 8; i++)
#pragma unroll
        for (int j = 0; j < 8; j++) acc[i][j] = 0.f;

    for (int k0 = 0; k0 < FIN; k0 += BK) {
        // load A tile 128x16 (512 float4, 2 per thread), transposed store
#pragma unroll
        for (int f = t; f < 512; f += 256) {
            int r = f >> 2, c = (f & 3) * 4;
            int gr = m0 + r;
            float4 v = make_float4(0.f, 0.f, 0.f, 0.f);
            if (gr < NN) v = *(const float4*)(A + (size_t)gr * FIN + k0 + c);
            As[c + 0][r] = v.x; As[c + 1][r] = v.y;
            As[c + 2][r] = v.z; As[c + 3][r] = v.w;
        }
        // load B tile 16x128 (512 float4, 2 per thread), coalesced
#pragma unroll
        for (int f = t; f < 512; f += 256) {
            int r = f >> 5, c = (f & 31) * 4;
            *(float4*)&Bs[r][c] = *(const float4*)(B + (size_t)(k0 + r) * HC + n0 + c);
        }
        __syncthreads();
#pragma unroll
        for (int k = 0; k < BK; k++) {
            float a[8], b[8];
            *(float4*)(a)     = *(float4*)&As[k][ty * 8];
            *(float4*)(a + 4) = *(float4*)&As[k][ty * 8 + 4];
            *(float4*)(b)     = *(float4*)&Bs[k][tx * 8];
            *(float4*)(b + 4) = *(float4*)&Bs[k][tx * 8 + 4];
#pragma unroll
            for (int i = 0; i < 8; i++)
#pragma unroll
                for (int j = 0; j < 8; j++) acc[i][j] += a[i] * b[j];
        }
        __syncthreads();
    }
#pragma unroll
    for (int i = 0; i < 8; i++) {
        int gr = m0 + ty * 8 + i;
        if (gr < NN) {
            *(float4*)(g_h1 + (size_t)gr * HC + n0 + tx * 8)     = *(float4*)&acc[i][0];
            *(float4*)(g_h1 + (size_t)gr * HC + n0 + tx * 8 + 4) = *(float4*)&acc[i][4];
        }
    }
}

// ---------------- per-node attention logits (layer 1): warp per node --------
__global__ void alpha1_kernel(const float* __restrict__ asrc,
                              const float* __restrict__ adst) {
    int warp = (blockIdx.x * blockDim.x + threadIdx.x) >> 5;
    int lane = threadIdx.x & 31;
    if (warp >= NN) return;
    const float* row = g_h1 + (size_t)warp * HC;
    float ps[HEADS], pd[HEADS];
#pragma unroll
    for (int h = 0; h < HEADS; h++) { ps[h] = 0.f; pd[h] = 0.f; }
#pragma unroll
    for (int h = 0; h < HEADS; h++)
#pragma unroll
        for (int j = 0; j < 4; j++) {
            int idx = (h * 4 + j) * 32 + lane;     // == h*128 + c
            float v = row[idx];
            ps[h] += v * asrc[idx];
            pd[h] += v * adst[idx];
        }
#pragma unroll
    for (int off = 16; off; off >>= 1)
#pragma unroll
        for (int h = 0; h < HEADS; h++) {
            ps[h] += __shfl_xor_sync(0xffffffffu, ps[h], off);
            pd[h] += __shfl_xor_sync(0xffffffffu, pd[h], off);
        }
    if (lane == 0)
#pragma unroll
        for (int h = 0; h < HEADS; h++) {
            g_as1[warp * HEADS + h] = ps[h];
            g_ad1[warp * HEADS + h] = pd[h];
        }
}

// ---------------- layer-1 edge passes ---------------------------------------
__global__ void edge_max1(const int* __restrict__ ei) {
    int tid = blockIdx.x * blockDim.x + threadIdx.x;
    if (tid >= ET * HEADS) return;
    int e = tid >> 2, h = tid & 3;
    int s, d;
    if (e < EE) { s = ei[e]; d = ei[EE + e]; } else { s = d = e - EE; }
    float ev = lrelu(g_as1[s * HEADS + h] + g_ad1[d * HEADS + h]);
    atomicMax(&g_mkey1[d * HEADS + h], fkey(ev));
}

__global__ void edge_exp1(const int* __restrict__ ei) {
    int tid = blockIdx.x * blockDim.x + threadIdx.x;
    if (tid >= ET * HEADS) return;
    int e = tid >> 2, h = tid & 3;
    int s, d;
    if (e < EE) { s = ei[e]; d = ei[EE + e]; } else { s = d = e - EE; }
    float ev = lrelu(g_as1[s * HEADS + h] + g_ad1[d * HEADS + h]);
    float p = expf(ev - funkey(g_mkey1[d * HEADS + h]));
    g_p1[tid] = p;
    atomicAdd(&g_den1[d * HEADS + h], p);
}

__global__ void edge_agg1(const int* __restrict__ ei) {
    int tid = blockIdx.x * blockDim.x + threadIdx.x;   // ET*128 float4 chunks
    if (tid >= (int)((size_t)ET * 128)) return;
    int e = tid >> 7, q = tid & 127, h = q >> 5;
    int s, d;
    if (e < EE) { s = ei[e]; d = ei[EE + e]; } else { s = d = e - EE; }
    float w = g_p1[(size_t)e * HEADS + h] / g_den1[d * HEADS + h];
    float4 v = ((const float4*)g_h1)[(size_t)s * 128 + q];
    v.x *= w; v.y *= w; v.z *= w; v.w *= w;
    float4* dst = ((float4*)g_out1) + (size_t)d * 128 + q;
    unsigned long long gp = __cvta_generic_to_global(dst);
    asm volatile("red.global.add.v4.f32 [%0], {%1,%2,%3,%4};"
                 :: "l"(gp), "f"(v.x), "f"(v.y), "f"(v.z), "f"(v.w) : "memory");
}

// --------- ELU + tiny GEMM2 (512x6) + layer-2 logits: warp per node ---------
__global__ void elu_gemm2_kernel(const float* __restrict__ b1,
                                 const float* __restrict__ W2,
                                 const float* __restrict__ asrc2,
                                 const float* __restrict__ adst2) {
    int warp = (blockIdx.x * blockDim.x + threadIdx.x) >> 5;
    int lane = threadIdx.x & 31;
    if (warp >= NN) return;
    const float* row = g_out1 + (size_t)warp * HC;
    float acc[CLS];
#pragma unroll
    for (int c = 0; c < CLS; c++) acc[c] = 0.f;
#pragma unroll
    for (int i = 0; i < 16; i++) {
        int k = lane + 32 * i;
        float a = row[k] + b1[k];
        a = a > 0.f ? a : expm1f(a);
#pragma unroll
        for (int c = 0; c < CLS; c++) acc[c] += a * W2[k * CLS + c];
    }
#pragma unroll
    for (int off = 16; off; off >>= 1)
#pragma unroll
        for (int c = 0; c < CLS; c++)
            acc[c] += __shfl_xor_sync(0xffffffffu, acc[c], off);
    if (lane == 0) {
        float s2 = 0.f, d2 = 0.f;
#pragma unroll
        for (int c = 0; c < CLS; c++) {
            g_h2[warp * CLS + c] = acc[c];
            s2 += acc[c] * asrc2[c];
            d2 += acc[c] * adst2[c];
        }
        g_as2[warp] = s2;
        g_ad2[warp] = d2;
    }
}

// ---------------- layer-2 edge passes ---------------------------------------
__global__ void edge_max2(const int* __restrict__ ei) {
    int e = blockIdx.x * blockDim.x + threadIdx.x;
    if (e >= ET) return;
    int s, d;
    if (e < EE) { s = ei[e]; d = ei[EE + e]; } else { s = d = e - EE; }
    float ev = lrelu(g_as2[s] + g_ad2[d]);
    atomicMax(&g_mkey2[d], fkey(ev));
}

__global__ void edge_exp2(const int* __restrict__ ei) {
    int e = blockIdx.x * blockDim.x + threadIdx.x;
    if (e >= ET) return;
    int s, d;
    if (e < EE) { s = ei[e]; d = ei[EE + e]; } else { s = d = e - EE; }
    float ev = lrelu(g_as2[s] + g_ad2[d]);
    float p = expf(ev - funkey(g_mkey2[d]));
    g_p2[e] = p;
    atomicAdd(&g_den2[d], p);
}

__global__ void edge_agg2(const int* __restrict__ ei, float* __restrict__ out) {
    int e = blockIdx.x * blockDim.x + threadIdx.x;
    if (e >= ET) return;
    int s, d;
    if (e < EE) { s = ei[e]; d = ei[EE + e]; } else { s = d = e - EE; }
    float w = g_p2[e] / g_den2[d];
#pragma unroll
    for (int c = 0; c < CLS; c++)
        atomicAdd(&out[d * CLS + c], g_h2[s * CLS + c] * w);
}

// ---------------- launch ----------------------------------------------------
extern "C" void kernel_launch(void* const* d_in, const int* in_sizes, int n_in,
                              void* d_out, int out_size) {
    const float* x     = (const float*)d_in[0];
    const int*   ei    = (const int*)d_in[1];
    const float* W1    = (const float*)d_in[2];
    const float* asrc1 = (const float*)d_in[3];
    const float* adst1 = (const float*)d_in[4];
    const float* b1    = (const float*)d_in[5];
    const float* W2    = (const float*)d_in[6];
    const float* asrc2 = (const float*)d_in[7];
    const float* adst2 = (const float*)d_in[8];
    const float* b2    = (const float*)d_in[9];
    float* out = (float*)d_out;

    init_kernel<<<(NN * HC + 255) / 256, 256>>>(b2, out);
    gemm1_kernel<<<dim3(HC / BN, (NN + BM - 1) / BM), 256>>>(x, W1);
    alpha1_kernel<<<(NN * 32 + 255) / 256, 256>>>(asrc1, adst1);
    edge_max1<<<(ET * HEADS + 255) / 256, 256>>>(ei);
    edge_exp1<<<(ET * HEADS + 255) / 256, 256>>>(ei);
    edge_agg1<<<(int)(((size_t)ET * 128 + 255) / 256), 256>>>(ei);
    elu_gemm2_kernel<<<(NN * 32 + 255) / 256, 256>>>(b1, W2, asrc2, adst2);
    edge_max2<<<(ET + 255) / 256, 256>>>(ei);
    edge_exp2<<<(ET + 255) / 256, 256>>>(ei);
    edge_agg2<<<(ET + 255) / 256, 256>>>(ei, out);
}

// round 2
// speedup vs baseline: 1.9928x; 1.9928x over previous
#include <cuda_runtime.h>
#include <cuda_bf16.h>
#include <math.h>

#define NN 30000
#define EE 480000
#define ET (EE + NN)          // edges + self loops
#define FIN 4096
#define HC 512                // HEADS*HID
#define HEADS 4
#define HID 128
#define CLS 6

// ---------------- scratch (static device globals; no runtime allocation) ----
__device__ float    g_h1[(size_t)NN * HC];     // x @ W1
__device__ float    g_out1[(size_t)NN * HC];   // layer-1 aggregation
__device__ float    g_w1t[(size_t)HC * FIN];   // W1^T, tf32-rounded
__device__ float    g_as1[NN * HEADS];
__device__ float    g_ad1[NN * HEADS];
__device__ unsigned g_mkey1[NN * HEADS];
__device__ float    g_den1[NN * HEADS];
__device__ float    g_p1[(size_t)ET * HEADS];
__device__ float    g_h2[NN * CLS];
__device__ float    g_as2[NN];
__device__ float    g_ad2[NN];
__device__ unsigned g_mkey2[NN];
__device__ float    g_den2[NN];
__device__ float    g_p2[ET];

// ---- monotone float->uint key for atomic max (sentinel 0 < key(-inf)) ------
__device__ __forceinline__ unsigned fkey(float f) {
    unsigned b = __float_as_uint(f);
    return (b & 0x80000000u) ? ~b : (b | 0x80000000u);
}
__device__ __forceinline__ float funkey(unsigned k) {
    return __uint_as_float((k & 0x80000000u) ? (k & 0x7FFFFFFFu) : ~k);
}
__device__ __forceinline__ float lrelu(float v) { return v > 0.f ? v : 0.2f * v; }
__device__ __forceinline__ unsigned tf32rna(float f) {
    unsigned u = __float_as_uint(f);
    asm("cvt.rna.tf32.f32 %0, %0;" : "+r"(u));
    return u;
}

// ---------------- init: zero accumulators, bias-init output -----------------
__global__ void init_kernel(const float* __restrict__ b2, float* __restrict__ out) {
    int i = blockIdx.x * blockDim.x + threadIdx.x;
    if (i < NN * HC)    g_out1[i] = 0.f;
    if (i < NN * HEADS) { g_den1[i] = 0.f; g_mkey1[i] = 0u; }
    if (i < NN)         { g_den2[i] = 0.f; g_mkey2[i] = 0u; }
    if (i < NN * CLS)   out[i] = b2[i % CLS];
}

// ---------------- transpose + tf32-round W1 into g_w1t ----------------------
__global__ void w1t_kernel(const float* __restrict__ W1) {
    int i = blockIdx.x * blockDim.x + threadIdx.x;
    if (i >= FIN * HC) return;
    int k = i / HC, n = i % HC;
    g_w1t[(size_t)n * FIN + k] = __uint_as_float(tf32rna(W1[i]));
}

// ---------------- GEMM1 (tensor cores, tf32): h1 = x @ W1 -------------------
// CTA tile 128x128, BK=16, 8 warps in 2x4, warp tile 64x32, mma m16n8k8.
#define GBK 16
#define ASTRIDE 20   // padded K stride (conflict-free for gid*20+tid pattern)

__device__ __forceinline__ void cp_async16(void* smem, const void* gmem, int bytes) {
    unsigned saddr = (unsigned)__cvta_generic_to_shared(smem);
    asm volatile("cp.async.ca.shared.global [%0], [%1], 16, %2;"
                 :: "r"(saddr), "l"(gmem), "r"(bytes));
}

__global__ __launch_bounds__(256, 2) void gemm1_tc(const float* __restrict__ A) {
    __shared__ float As[2][128][ASTRIDE];
    __shared__ float Bs[2][128][ASTRIDE];
    const int t     = threadIdx.x;
    const int m0    = blockIdx.y * 128;
    const int n0    = blockIdx.x * 128;
    const int wid   = t >> 5;
    const int lane  = t & 31;
    const int gid   = lane >> 2;       // 0..7
    const int tid4  = lane & 3;        // 0..3
    const int wm    = (wid >> 2) * 64; // warp row base
    const int wn    = (wid & 3) * 32;  // warp col base

    float acc[4][4][4];
#pragma unroll
    for (int i = 0; i < 4; i++)
#pragma unroll
        for (int j = 0; j < 4; j++)
#pragma unroll
            for (int r = 0; r < 4; r++) acc[i][j][r] = 0.f;

    // per-thread load coords (2 float4 each for A and B per stage)
    const int r0 = t >> 1;             // 0..127 (two threads per row)
    const int c0 = (t & 1) * 8;        // 0 or 8

    auto load_stage = [&](int buf, int k0) {
#pragma unroll
        for (int h = 0; h < 2; h++) {
            int gr = m0 + r0;
            int cc = c0 + h * 4;
            cp_async16(&As[buf][r0][cc], A + (size_t)gr * FIN + k0 + cc,
                       gr < NN ? 16 : 0);
            cp_async16(&Bs[buf][r0][cc], g_w1t + (size_t)(n0 + r0) * FIN + k0 + cc, 16);
        }
        asm volatile("cp.async.commit_group;");
    };

    load_stage(0, 0);

    const int NT = FIN / GBK;  // 256
    for (int kt = 0; kt < NT; kt++) {
        asm volatile("cp.async.wait_group 0;");
        __syncthreads();
        int buf = kt & 1;
        if (kt + 1 < NT) load_stage(buf ^ 1, (kt + 1) * GBK);

#pragma unroll
        for (int kk = 0; kk < GBK; kk += 8) {
            unsigned af[4][4], bf[4][2];
#pragma unroll
            for (int mt = 0; mt < 4; mt++) {
                int r = wm + mt * 16 + gid;
                af[mt][0] = tf32rna(As[buf][r][kk + tid4]);
                af[mt][1] = tf32rna(As[buf][r + 8][kk + tid4]);
                af[mt][2] = tf32rna(As[buf][r][kk + tid4 + 4]);
                af[mt][3] = tf32rna(As[buf][r + 8][kk + tid4 + 4]);
            }
#pragma unroll
            for (int nt = 0; nt < 4; nt++) {
                int c = wn + nt * 8 + gid;
                bf[nt][0] = __float_as_uint(Bs[buf][c][kk + tid4]);
                bf[nt][1] = __float_as_uint(Bs[buf][c][kk + tid4 + 4]);
            }
#pragma unroll
            for (int mt = 0; mt < 4; mt++)
#pragma unroll
                for (int nt = 0; nt < 4; nt++) {
                    asm volatile(
                        "mma.sync.aligned.m16n8k8.row.col.f32.tf32.tf32.f32 "
                        "{%0,%1,%2,%3}, {%4,%5,%6,%7}, {%8,%9}, {%0,%1,%2,%3};"
                        : "+f"(acc[mt][nt][0]), "+f"(acc[mt][nt][1]),
                          "+f"(acc[mt][nt][2]), "+f"(acc[mt][nt][3])
                        : "r"(af[mt][0]), "r"(af[mt][1]),
                          "r"(af[mt][2]), "r"(af[mt][3]),
                          "r"(bf[nt][0]), "r"(bf[nt][1]));
                }
        }
        __syncthreads();
    }

    // epilogue: c0,c1 -> (row gid, cols 2tid,2tid+1); c2,c3 -> row gid+8
#pragma unroll
    for (int mt = 0; mt < 4; mt++) {
        int r1 = m0 + wm + mt * 16 + gid;
        int r2 = r1 + 8;
#pragma unroll
        for (int nt = 0; nt < 4; nt++) {
            int c = n0 + wn + nt * 8 + tid4 * 2;
            if (r1 < NN) *(float2*)(g_h1 + (size_t)r1 * HC + c) =
                make_float2(acc[mt][nt][0], acc[mt][nt][1]);
            if (r2 < NN) *(float2*)(g_h1 + (size_t)r2 * HC + c) =
                make_float2(acc[mt][nt][2], acc[mt][nt][3]);
        }
    }
}

// ---------------- per-node attention logits (layer 1): warp per node --------
__global__ void alpha1_kernel(const float* __restrict__ asrc,
                              const float* __restrict__ adst) {
    int warp = (blockIdx.x * blockDim.x + threadIdx.x) >> 5;
    int lane = threadIdx.x & 31;
    if (warp >= NN) return;
    const float* row = g_h1 + (size_t)warp * HC;
    float ps[HEADS], pd[HEADS];
#pragma unroll
    for (int h = 0; h < HEADS; h++) { ps[h] = 0.f; pd[h] = 0.f; }
#pragma unroll
    for (int h = 0; h < HEADS; h++)
#pragma unroll
        for (int j = 0; j < 4; j++) {
            int idx = (h * 4 + j) * 32 + lane;
            float v = row[idx];
            ps[h] += v * asrc[idx];
            pd[h] += v * adst[idx];
        }
#pragma unroll
    for (int off = 16; off; off >>= 1)
#pragma unroll
        for (int h = 0; h < HEADS; h++) {
            ps[h] += __shfl_xor_sync(0xffffffffu, ps[h], off);
            pd[h] += __shfl_xor_sync(0xffffffffu, pd[h], off);
        }
    if (lane == 0)
#pragma unroll
        for (int h = 0; h < HEADS; h++) {
            g_as1[warp * HEADS + h] = ps[h];
            g_ad1[warp * HEADS + h] = pd[h];
        }
}

// ---------------- layer-1 edge passes ---------------------------------------
__global__ void edge_max1(const int* __restrict__ ei) {
    int tid = blockIdx.x * blockDim.x + threadIdx.x;
    if (tid >= ET * HEADS) return;
    int e = tid >> 2, h = tid & 3;
    int s, d;
    if (e < EE) { s = ei[e]; d = ei[EE + e]; } else { s = d = e - EE; }
    float ev = lrelu(g_as1[s * HEADS + h] + g_ad1[d * HEADS + h]);
    atomicMax(&g_mkey1[d * HEADS + h], fkey(ev));
}

__global__ void edge_exp1(const int* __restrict__ ei) {
    int tid = blockIdx.x * blockDim.x + threadIdx.x;
    if (tid >= ET * HEADS) return;
    int e = tid >> 2, h = tid & 3;
    int s, d;
    if (e < EE) { s = ei[e]; d = ei[EE + e]; } else { s = d = e - EE; }
    float ev = lrelu(g_as1[s * HEADS + h] + g_ad1[d * HEADS + h]);
    float p = expf(ev - funkey(g_mkey1[d * HEADS + h]));
    g_p1[tid] = p;
    atomicAdd(&g_den1[d * HEADS + h], p);
}

__global__ void edge_agg1(const int* __restrict__ ei) {
    int tid = blockIdx.x * blockDim.x + threadIdx.x;   // ET*128 float4 chunks
    if (tid >= (int)((size_t)ET * 128)) return;
    int e = tid >> 7, q = tid & 127, h = q >> 5;
    int s, d;
    if (e < EE) { s = ei[e]; d = ei[EE + e]; } else { s = d = e - EE; }
    float w = g_p1[(size_t)e * HEADS + h] / g_den1[d * HEADS + h];
    float4 v = ((const float4*)g_h1)[(size_t)s * 128 + q];
    v.x *= w; v.y *= w; v.z *= w; v.w *= w;
    float4* dst = ((float4*)g_out1) + (size_t)d * 128 + q;
    unsigned long long gp = __cvta_generic_to_global(dst);
    asm volatile("red.global.add.v4.f32 [%0], {%1,%2,%3,%4};"
                 :: "l"(gp), "f"(v.x), "f"(v.y), "f"(v.z), "f"(v.w) : "memory");
}

// --------- ELU + tiny GEMM2 (512x6) + layer-2 logits: warp per node ---------
__global__ void elu_gemm2_kernel(const float* __restrict__ b1,
                                 const float* __restrict__ W2,
                                 const float* __restrict__ asrc2,
                                 const float* __restrict__ adst2) {
    int warp = (blockIdx.x * blockDim.x + threadIdx.x) >> 5;
    int lane = threadIdx.x & 31;
    if (warp >= NN) return;
    const float* row = g_out1 + (size_t)warp * HC;
    float acc[CLS];
#pragma unroll
    for (int c = 0; c < CLS; c++) acc[c] = 0.f;
#pragma unroll
    for (int i = 0; i < 16; i++) {
        int k = lane + 32 * i;
        float a = row[k] + b1[k];
        a = a > 0.f ? a : expm1f(a);
#pragma unroll
        for (int c = 0; c < CLS; c++) acc[c] += a * W2[k * CLS + c];
    }
#pragma unroll
    for (int off = 16; off; off >>= 1)
#pragma unroll
        for (int c = 0; c < CLS; c++)
            acc[c] += __shfl_xor_sync(0xffffffffu, acc[c], off);
    if (lane == 0) {
        float s2 = 0.f, d2 = 0.f;
#pragma unroll
        for (int c = 0; c < CLS; c++) {
            g_h2[warp * CLS + c] = acc[c];
            s2 += acc[c] * asrc2[c];
            d2 += acc[c] * adst2[c];
        }
        g_as2[warp] = s2;
        g_ad2[warp] = d2;
    }
}

// ---------------- layer-2 edge passes ---------------------------------------
__global__ void edge_max2(const int* __restrict__ ei) {
    int e = blockIdx.x * blockDim.x + threadIdx.x;
    if (e >= ET) return;
    int s, d;
    if (e < EE) { s = ei[e]; d = ei[EE + e]; } else { s = d = e - EE; }
    float ev = lrelu(g_as2[s] + g_ad2[d]);
    atomicMax(&g_mkey2[d], fkey(ev));
}

__global__ void edge_exp2(const int* __restrict__ ei) {
    int e = blockIdx.x * blockDim.x + threadIdx.x;
    if (e >= ET) return;
    int s, d;
    if (e < EE) { s = ei[e]; d = ei[EE + e]; } else { s = d = e - EE; }
    float ev = lrelu(g_as2[s] + g_ad2[d]);
    float p = expf(ev - funkey(g_mkey2[d]));
    g_p2[e] = p;
    atomicAdd(&g_den2[d], p);
}

__global__ void edge_agg2(const int* __restrict__ ei, float* __restrict__ out) {
    int e = blockIdx.x * blockDim.x + threadIdx.x;
    if (e >= ET) return;
    int s, d;
    if (e < EE) { s = ei[e]; d = ei[EE + e]; } else { s = d = e - EE; }
    float w = g_p2[e] / g_den2[d];
#pragma unroll
    for (int c = 0; c < CLS; c++)
        atomicAdd(&out[d * CLS + c], g_h2[s * CLS + c] * w);
}

// ---------------- launch ----------------------------------------------------
extern "C" void kernel_launch(void* const* d_in, const int* in_sizes, int n_in,
                              void* d_out, int out_size) {
    const float* x     = (const float*)d_in[0];
    const int*   ei    = (const int*)d_in[1];
    const float* W1    = (const float*)d_in[2];
    const float* asrc1 = (const float*)d_in[3];
    const float* adst1 = (const float*)d_in[4];
    const float* b1    = (const float*)d_in[5];
    const float* W2    = (const float*)d_in[6];
    const float* asrc2 = (const float*)d_in[7];
    const float* adst2 = (const float*)d_in[8];
    const float* b2    = (const float*)d_in[9];
    float* out = (float*)d_out;

    init_kernel<<<(NN * HC + 255) / 256, 256>>>(b2, out);
    w1t_kernel<<<(FIN * HC + 255) / 256, 256>>>(W1);
    gemm1_tc<<<dim3(HC / 128, (NN + 127) / 128), 256>>>(x);
    alpha1_kernel<<<(NN * 32 + 255) / 256, 256>>>(asrc1, adst1);
    edge_max1<<<(ET * HEADS + 255) / 256, 256>>>(ei);
    edge_exp1<<<(ET * HEADS + 255) / 256, 256>>>(ei);
    edge_agg1<<<(int)(((size_t)ET * 128 + 255) / 256), 256>>>(ei);
    elu_gemm2_kernel<<<(NN * 32 + 255) / 256, 256>>>(b1, W2, asrc2, adst2);
    edge_max2<<<(ET + 255) / 256, 256>>>(ei);
    edge_exp2<<<(ET + 255) / 256, 256>>>(ei);
    edge_agg2<<<(ET + 255) / 256, 256>>>(ei, out);
}

// round 3
// speedup vs baseline: 2.3112x; 1.1598x over previous
#include <cuda_runtime.h>
#include <cuda_bf16.h>
#include <math.h>

#define NN 30000
#define EE 480000
#define ET (EE + NN)          // edges + self loops
#define FIN 4096
#define HC 512                // HEADS*HID
#define HEADS 4
#define HID 128
#define CLS 6

// ---------------- scratch (static device globals; no runtime allocation) ----
__device__ float    g_h1[(size_t)NN * HC];     // x @ W1
__device__ float    g_out1[(size_t)NN * HC];   // layer-1 aggregation
__device__ float    g_w1t[(size_t)HC * FIN];   // W1^T, tf32-rounded
__device__ float    g_as1[NN * HEADS];
__device__ float    g_ad1[NN * HEADS];
__device__ float    g_h2[NN * CLS];
__device__ float    g_as2[NN];
__device__ float    g_ad2[NN];
// CSR by destination
__device__ int      g_deg[NN];
__device__ int      g_off[NN + 1];
__device__ int      g_pos[NN];
__device__ int      g_esrc[ET];

__device__ __forceinline__ float lrelu(float v) { return v > 0.f ? v : 0.2f * v; }
__device__ __forceinline__ unsigned tf32rna(float f) {
    unsigned u = __float_as_uint(f);
    asm("cvt.rna.tf32.f32 %0, %0;" : "+r"(u));
    return u;
}
__device__ __forceinline__ void edge_sd(const int* __restrict__ ei, int e,
                                        int& s, int& d) {
    if (e < EE) { s = ei[e]; d = ei[EE + e]; } else { s = d = e - EE; }
}

// ---------------- CSR build --------------------------------------------------
__global__ void zero_deg_kernel() {
    int i = blockIdx.x * blockDim.x + threadIdx.x;
    if (i < NN) g_deg[i] = 0;
}
__global__ void count_kernel(const int* __restrict__ ei) {
    int e = blockIdx.x * blockDim.x + threadIdx.x;
    if (e >= ET) return;
    int s, d; edge_sd(ei, e, s, d);
    atomicAdd(&g_deg[d], 1);
}
__global__ void scan_kernel() {   // single block, 1024 threads
    __shared__ int partial[1024];
    const int t = threadIdx.x;
    const int CH = (NN + 1023) / 1024;   // 30
    const int base = t * CH;
    int sum = 0;
    for (int c = 0; c < CH; c++) {
        int i = base + c;
        if (i < NN) sum += g_deg[i];
    }
    partial[t] = sum;
    __syncthreads();
    for (int off = 1; off < 1024; off <<= 1) {
        int v = (t >= off) ? partial[t - off] : 0;
        __syncthreads();
        partial[t] += v;
        __syncthreads();
    }
    int acc = partial[t] - sum;          // exclusive prefix
    for (int c = 0; c < CH; c++) {
        int i = base + c;
        if (i < NN) { g_off[i] = acc; g_pos[i] = acc; acc += g_deg[i]; }
    }
    if (t == 0) g_off[NN] = ET;
}
__global__ void scatter_kernel(const int* __restrict__ ei) {
    int e = blockIdx.x * blockDim.x + threadIdx.x;
    if (e >= ET) return;
    int s, d; edge_sd(ei, e, s, d);
    int p = atomicAdd(&g_pos[d], 1);
    g_esrc[p] = s;
}

// ---------------- transpose + tf32-round W1 into g_w1t ----------------------
__global__ void w1t_kernel(const float* __restrict__ W1) {
    int i = blockIdx.x * blockDim.x + threadIdx.x;
    if (i >= FIN * HC) return;
    int k = i / HC, n = i % HC;
    g_w1t[(size_t)n * FIN + k] = __uint_as_float(tf32rna(W1[i]));
}

// ---------------- GEMM1 (tensor cores, tf32): h1 = x @ W1 -------------------
#define GBK 16
#define ASTRIDE 20

__device__ __forceinline__ void cp_async16(void* smem, const void* gmem, int bytes) {
    unsigned saddr = (unsigned)__cvta_generic_to_shared(smem);
    asm volatile("cp.async.ca.shared.global [%0], [%1], 16, %2;"
                 :: "r"(saddr), "l"(gmem), "r"(bytes));
}

__global__ __launch_bounds__(256, 2) void gemm1_tc(const float* __restrict__ A) {
    __shared__ float As[2][128][ASTRIDE];
    __shared__ float Bs[2][128][ASTRIDE];
    const int t     = threadIdx.x;
    const int m0    = blockIdx.y * 128;
    const int n0    = blockIdx.x * 128;
    const int wid   = t >> 5;
    const int lane  = t & 31;
    const int gid   = lane >> 2;
    const int tid4  = lane & 3;
    const int wm    = (wid >> 2) * 64;
    const int wn    = (wid & 3) * 32;

    float acc[4][4][4];
#pragma unroll
    for (int i = 0; i < 4; i++)
#pragma unroll
        for (int j = 0; j < 4; j++)
#pragma unroll
            for (int r = 0; r < 4; r++) acc[i][j][r] = 0.f;

    const int r0 = t >> 1;
    const int c0 = (t & 1) * 8;

    auto load_stage = [&](int buf, int k0) {
#pragma unroll
        for (int h = 0; h < 2; h++) {
            int gr = m0 + r0;
            int cc = c0 + h * 4;
            cp_async16(&As[buf][r0][cc], A + (size_t)gr * FIN + k0 + cc,
                       gr < NN ? 16 : 0);
            cp_async16(&Bs[buf][r0][cc], g_w1t + (size_t)(n0 + r0) * FIN + k0 + cc, 16);
        }
        asm volatile("cp.async.commit_group;");
    };

    load_stage(0, 0);

    const int NT = FIN / GBK;
    for (int kt = 0; kt < NT; kt++) {
        asm volatile("cp.async.wait_group 0;");
        __syncthreads();
        int buf = kt & 1;
        if (kt + 1 < NT) load_stage(buf ^ 1, (kt + 1) * GBK);

#pragma unroll
        for (int kk = 0; kk < GBK; kk += 8) {
            unsigned af[4][4], bf[4][2];
#pragma unroll
            for (int mt = 0; mt < 4; mt++) {
                int r = wm + mt * 16 + gid;
                af[mt][0] = tf32rna(As[buf][r][kk + tid4]);
                af[mt][1] = tf32rna(As[buf][r + 8][kk + tid4]);
                af[mt][2] = tf32rna(As[buf][r][kk + tid4 + 4]);
                af[mt][3] = tf32rna(As[buf][r + 8][kk + tid4 + 4]);
            }
#pragma unroll
            for (int nt = 0; nt < 4; nt++) {
                int c = wn + nt * 8 + gid;
                bf[nt][0] = __float_as_uint(Bs[buf][c][kk + tid4]);
                bf[nt][1] = __float_as_uint(Bs[buf][c][kk + tid4 + 4]);
            }
#pragma unroll
            for (int mt = 0; mt < 4; mt++)
#pragma unroll
                for (int nt = 0; nt < 4; nt++) {
                    asm volatile(
                        "mma.sync.aligned.m16n8k8.row.col.f32.tf32.tf32.f32 "
                        "{%0,%1,%2,%3}, {%4,%5,%6,%7}, {%8,%9}, {%0,%1,%2,%3};"
                        : "+f"(acc[mt][nt][0]), "+f"(acc[mt][nt][1]),
                          "+f"(acc[mt][nt][2]), "+f"(acc[mt][nt][3])
                        : "r"(af[mt][0]), "r"(af[mt][1]),
                          "r"(af[mt][2]), "r"(af[mt][3]),
                          "r"(bf[nt][0]), "r"(bf[nt][1]));
                }
        }
        __syncthreads();
    }

#pragma unroll
    for (int mt = 0; mt < 4; mt++) {
        int r1 = m0 + wm + mt * 16 + gid;
        int r2 = r1 + 8;
#pragma unroll
        for (int nt = 0; nt < 4; nt++) {
            int c = n0 + wn + nt * 8 + tid4 * 2;
            if (r1 < NN) *(float2*)(g_h1 + (size_t)r1 * HC + c) =
                make_float2(acc[mt][nt][0], acc[mt][nt][1]);
            if (r2 < NN) *(float2*)(g_h1 + (size_t)r2 * HC + c) =
                make_float2(acc[mt][nt][2], acc[mt][nt][3]);
        }
    }
}

// ---------------- per-node attention logits (layer 1): warp per node --------
__global__ void alpha1_kernel(const float* __restrict__ asrc,
                              const float* __restrict__ adst) {
    int warp = (blockIdx.x * blockDim.x + threadIdx.x) >> 5;
    int lane = threadIdx.x & 31;
    if (warp >= NN) return;
    const float* row = g_h1 + (size_t)warp * HC;
    float ps[HEADS], pd[HEADS];
#pragma unroll
    for (int h = 0; h < HEADS; h++) { ps[h] = 0.f; pd[h] = 0.f; }
#pragma unroll
    for (int h = 0; h < HEADS; h++)
#pragma unroll
        for (int j = 0; j < 4; j++) {
            int idx = (h * 4 + j) * 32 + lane;
            float v = row[idx];
            ps[h] += v * asrc[idx];
            pd[h] += v * adst[idx];
        }
#pragma unroll
    for (int off = 16; off; off >>= 1)
#pragma unroll
        for (int h = 0; h < HEADS; h++) {
            ps[h] += __shfl_xor_sync(0xffffffffu, ps[h], off);
            pd[h] += __shfl_xor_sync(0xffffffffu, pd[h], off);
        }
    if (lane == 0)
#pragma unroll
        for (int h = 0; h < HEADS; h++) {
            g_as1[warp * HEADS + h] = ps[h];
            g_ad1[warp * HEADS + h] = pd[h];
        }
}

// ------------- fused layer-1 softmax + aggregate: warp per dst node ---------
__global__ __launch_bounds__(256) void fused_agg1() {
    int d    = (blockIdx.x * blockDim.x + threadIdx.x) >> 5;
    int lane = threadIdx.x & 31;
    if (d >= NN) return;
    const int beg = g_off[d], end = g_off[d + 1];
    const float4 ad = *(const float4*)(g_ad1 + d * 4);

    // pass 1: per-head max
    float m0 = -1e30f, m1 = -1e30f, m2 = -1e30f, m3 = -1e30f;
    for (int i = beg + lane; i < end; i += 32) {
        int s = g_esrc[i];
        float4 as = *(const float4*)(g_as1 + s * 4);
        m0 = fmaxf(m0, lrelu(as.x + ad.x));
        m1 = fmaxf(m1, lrelu(as.y + ad.y));
        m2 = fmaxf(m2, lrelu(as.z + ad.z));
        m3 = fmaxf(m3, lrelu(as.w + ad.w));
    }
#pragma unroll
    for (int off = 16; off; off >>= 1) {
        m0 = fmaxf(m0, __shfl_xor_sync(0xffffffffu, m0, off));
        m1 = fmaxf(m1, __shfl_xor_sync(0xffffffffu, m1, off));
        m2 = fmaxf(m2, __shfl_xor_sync(0xffffffffu, m2, off));
        m3 = fmaxf(m3, __shfl_xor_sync(0xffffffffu, m3, off));
    }
    // pass 2: denominators
    float d0 = 0.f, d1 = 0.f, d2 = 0.f, d3 = 0.f;
    for (int i = beg + lane; i < end; i += 32) {
        int s = g_esrc[i];
        float4 as = *(const float4*)(g_as1 + s * 4);
        d0 += expf(lrelu(as.x + ad.x) - m0);
        d1 += expf(lrelu(as.y + ad.y) - m1);
        d2 += expf(lrelu(as.z + ad.z) - m2);
        d3 += expf(lrelu(as.w + ad.w) - m3);
    }
#pragma unroll
    for (int off = 16; off; off >>= 1) {
        d0 += __shfl_xor_sync(0xffffffffu, d0, off);
        d1 += __shfl_xor_sync(0xffffffffu, d1, off);
        d2 += __shfl_xor_sync(0xffffffffu, d2, off);
        d3 += __shfl_xor_sync(0xffffffffu, d3, off);
    }
    const float r0 = 1.f / d0, r1 = 1.f / d1, r2 = 1.f / d2, r3 = 1.f / d3;

    // pass 3: weighted gather; lane owns float4 at head h, offset lane*4
    float4 a0 = {0,0,0,0}, a1 = {0,0,0,0}, a2 = {0,0,0,0}, a3 = {0,0,0,0};
    for (int i = beg; i < end; i++) {
        int s = g_esrc[i];                                     // broadcast
        float4 as = *(const float4*)(g_as1 + s * 4);           // broadcast
        float w0 = expf(lrelu(as.x + ad.x) - m0) * r0;
        float w1 = expf(lrelu(as.y + ad.y) - m1) * r1;
        float w2 = expf(lrelu(as.z + ad.z) - m2) * r2;
        float w3 = expf(lrelu(as.w + ad.w) - m3) * r3;
        const float4* row = (const float4*)(g_h1 + (size_t)s * HC);
        float4 v;
        v = row[lane];      a0.x += w0*v.x; a0.y += w0*v.y; a0.z += w0*v.z; a0.w += w0*v.w;
        v = row[32 + lane]; a1.x += w1*v.x; a1.y += w1*v.y; a1.z += w1*v.z; a1.w += w1*v.w;
        v = row[64 + lane]; a2.x += w2*v.x; a2.y += w2*v.y; a2.z += w2*v.z; a2.w += w2*v.w;
        v = row[96 + lane]; a3.x += w3*v.x; a3.y += w3*v.y; a3.z += w3*v.z; a3.w += w3*v.w;
    }
    float4* orow = (float4*)(g_out1 + (size_t)d * HC);
    orow[lane]      = a0;
    orow[32 + lane] = a1;
    orow[64 + lane] = a2;
    orow[96 + lane] = a3;
}

// --------- ELU + tiny GEMM2 (512x6) + layer-2 logits: warp per node ---------
__global__ void elu_gemm2_kernel(const float* __restrict__ b1,
                                 const float* __restrict__ W2,
                                 const float* __restrict__ asrc2,
                                 const float* __restrict__ adst2) {
    int warp = (blockIdx.x * blockDim.x + threadIdx.x) >> 5;
    int lane = threadIdx.x & 31;
    if (warp >= NN) return;
    const float* row = g_out1 + (size_t)warp * HC;
    float acc[CLS];
#pragma unroll
    for (int c = 0; c < CLS; c++) acc[c] = 0.f;
#pragma unroll
    for (int i = 0; i < 16; i++) {
        int k = lane + 32 * i;
        float a = row[k] + b1[k];
        a = a > 0.f ? a : expm1f(a);
#pragma unroll
        for (int c = 0; c < CLS; c++) acc[c] += a * W2[k * CLS + c];
    }
#pragma unroll
    for (int off = 16; off; off >>= 1)
#pragma unroll
        for (int c = 0; c < CLS; c++)
            acc[c] += __shfl_xor_sync(0xffffffffu, acc[c], off);
    if (lane == 0) {
        float s2 = 0.f, d2 = 0.f;
#pragma unroll
        for (int c = 0; c < CLS; c++) {
            g_h2[warp * CLS + c] = acc[c];
            s2 += acc[c] * asrc2[c];
            d2 += acc[c] * adst2[c];
        }
        g_as2[warp] = s2;
        g_ad2[warp] = d2;
    }
}

// ------------- fused layer-2 softmax + aggregate: warp per dst node ---------
__global__ __launch_bounds__(256) void fused_agg2(const float* __restrict__ b2,
                                                  float* __restrict__ out) {
    int d    = (blockIdx.x * blockDim.x + threadIdx.x) >> 5;
    int lane = threadIdx.x & 31;
    if (d >= NN) return;
    const int beg = g_off[d], end = g_off[d + 1];
    const float ad = g_ad2[d];

    float m = -1e30f;
    for (int i = beg + lane; i < end; i += 32)
        m = fmaxf(m, lrelu(g_as2[g_esrc[i]] + ad));
#pragma unroll
    for (int off = 16; off; off >>= 1)
        m = fmaxf(m, __shfl_xor_sync(0xffffffffu, m, off));

    float den = 0.f;
    for (int i = beg + lane; i < end; i += 32)
        den += expf(lrelu(g_as2[g_esrc[i]] + ad) - m);
#pragma unroll
    for (int off = 16; off; off >>= 1)
        den += __shfl_xor_sync(0xffffffffu, den, off);
    const float rden = 1.f / den;

    float acc[CLS];
#pragma unroll
    for (int c = 0; c < CLS; c++) acc[c] = 0.f;
    for (int i = beg + lane; i < end; i += 32) {
        int s = g_esrc[i];
        float w = expf(lrelu(g_as2[s] + ad) - m) * rden;
#pragma unroll
        for (int c = 0; c < CLS; c++) acc[c] += w * g_h2[s * CLS + c];
    }
#pragma unroll
    for (int off = 16; off; off >>= 1)
#pragma unroll
        for (int c = 0; c < CLS; c++)
            acc[c] += __shfl_xor_sync(0xffffffffu, acc[c], off);
    if (lane == 0)
#pragma unroll
        for (int c = 0; c < CLS; c++)
            out[d * CLS + c] = acc[c] + b2[c];
}

// ---------------- launch ----------------------------------------------------
extern "C" void kernel_launch(void* const* d_in, const int* in_sizes, int n_in,
                              void* d_out, int out_size) {
    const float* x     = (const float*)d_in[0];
    const int*   ei    = (const int*)d_in[1];
    const float* W1    = (const float*)d_in[2];
    const float* asrc1 = (const float*)d_in[3];
    const float* adst1 = (const float*)d_in[4];
    const float* b1    = (const float*)d_in[5];
    const float* W2    = (const float*)d_in[6];
    const float* asrc2 = (const float*)d_in[7];
    const float* adst2 = (const float*)d_in[8];
    const float* b2    = (const float*)d_in[9];
    float* out = (float*)d_out;

    // CSR build (independent of GEMM)
    zero_deg_kernel<<<(NN + 255) / 256, 256>>>();
    count_kernel<<<(ET + 255) / 256, 256>>>(ei);
    scan_kernel<<<1, 1024>>>();
    scatter_kernel<<<(ET + 255) / 256, 256>>>(ei);

    w1t_kernel<<<(FIN * HC + 255) / 256, 256>>>(W1);
    gemm1_tc<<<dim3(HC / 128, (NN + 127) / 128), 256>>>(x);
    alpha1_kernel<<<(NN * 32 + 255) / 256, 256>>>(asrc1, adst1);
    fused_agg1<<<(NN * 32 + 255) / 256, 256>>>();
    elu_gemm2_kernel<<<(NN * 32 + 255) / 256, 256>>>(b1, W2, asrc2, adst2);
    fused_agg2<<<(NN * 32 + 255) / 256, 256>>>(b2, out);
}

// round 5
// speedup vs baseline: 3.5998x; 1.5575x over previous
#include <cuda_runtime.h>
#include <cuda_bf16.h>
#include <math.h>
#include <stdint.h>

#define NN 30000
#define EE 480000
#define ET (EE + NN)
#define FIN 4096
#define HC 512
#define HEADS 4
#define HID 128
#define CLS 6

// ---------------- scratch (static device globals) ---------------------------
__device__ float    g_h1[(size_t)NN * HC];
__device__ float    g_out1[(size_t)NN * HC];
__device__ float    g_w1t[(size_t)HC * FIN];   // W1^T, tf32-rounded, K-major
__device__ float    g_as1[NN * HEADS];
__device__ float    g_ad1[NN * HEADS];
__device__ float    g_h2[NN * CLS];
__device__ float    g_as2[NN];
__device__ float    g_ad2[NN];
__device__ int      g_deg[NN];
__device__ int      g_off[NN + 1];
__device__ int      g_pos[NN];
__device__ int      g_esrc[ET];

__device__ __forceinline__ float lrelu(float v) { return v > 0.f ? v : 0.2f * v; }
__device__ __forceinline__ unsigned tf32rna(float f) {
    unsigned u = __float_as_uint(f);
    asm("cvt.rna.tf32.f32 %0, %0;" : "+r"(u));
    return u;
}
__device__ __forceinline__ void edge_sd(const int* __restrict__ ei, int e,
                                        int& s, int& d) {
    if (e < EE) { s = ei[e]; d = ei[EE + e]; } else { s = d = e - EE; }
}
__device__ __forceinline__ uint32_t smem_u32(const void* p) {
    uint32_t a;
    asm("{ .reg .u64 t; cvta.to.shared.u64 t, %1; cvt.u32.u64 %0, t; }"
        : "=r"(a) : "l"(p));
    return a;
}
__device__ __forceinline__ void cp16(uint32_t saddr, const void* g, int bytes) {
    asm volatile("cp.async.ca.shared.global [%0], [%1], 16, %2;"
                 :: "r"(saddr), "l"(g), "r"(bytes));
}

// ---------------- CSR build --------------------------------------------------
__global__ void zero_deg_kernel() {
    int i = blockIdx.x * blockDim.x + threadIdx.x;
    if (i < NN) g_deg[i] = 0;
}
__global__ void count_kernel(const int* __restrict__ ei) {
    int e = blockIdx.x * blockDim.x + threadIdx.x;
    if (e >= ET) return;
    int s, d; edge_sd(ei, e, s, d);
    atomicAdd(&g_deg[d], 1);
}
__global__ void scan_kernel() {
    __shared__ int partial[1024];
    const int t = threadIdx.x;
    const int CH = (NN + 1023) / 1024;
    const int base = t * CH;
    int sum = 0;
    for (int c = 0; c < CH; c++) { int i = base + c; if (i < NN) sum += g_deg[i]; }
    partial[t] = sum;
    __syncthreads();
    for (int off = 1; off < 1024; off <<= 1) {
        int v = (t >= off) ? partial[t - off] : 0;
        __syncthreads();
        partial[t] += v;
        __syncthreads();
    }
    int acc = partial[t] - sum;
    for (int c = 0; c < CH; c++) {
        int i = base + c;
        if (i < NN) { g_off[i] = acc; g_pos[i] = acc; acc += g_deg[i]; }
    }
    if (t == 0) g_off[NN] = ET;
}
__global__ void scatter_kernel(const int* __restrict__ ei) {
    int e = blockIdx.x * blockDim.x + threadIdx.x;
    if (e >= ET) return;
    int s, d; edge_sd(ei, e, s, d);
    int p = atomicAdd(&g_pos[d], 1);
    g_esrc[p] = s;
}

// ---------------- transpose + tf32-round W1 ----------------------------------
__global__ void w1t_kernel(const float* __restrict__ W1) {
    int i = blockIdx.x * blockDim.x + threadIdx.x;
    if (i >= FIN * HC) return;
    int k = i / HC, n = i % HC;
    g_w1t[(size_t)n * FIN + k] = __uint_as_float(tf32rna(W1[i]));
}

// ---------------- GEMM1 (mma.sync tf32): h1 = x @ W1 ------------------------
// CTA tile 128x256, BK=32, 3-stage cp.async pipeline, 8 warps (2x4),
// warp tile 64x64, mma m16n8k8.
#define BM 128
#define BN 256
#define BK2 32
#define ASTR 36                       // padded row stride (floats)
#define A_STAGE (BM * ASTR)           // 4608 floats
#define B_STAGE (BN * ASTR)           // 9216 floats
#define SMEM_BYTES (3 * (A_STAGE + B_STAGE) * 4)   // 165888

__global__ __launch_bounds__(256, 1) void gemm1_tc(const float* __restrict__ A) {
    extern __shared__ float sm[];
    float* Asm = sm;                    // [3][128][36]
    float* Bsm = sm + 3 * A_STAGE;      // [3][256][36]
    const int t    = threadIdx.x;
    const int m0   = blockIdx.y * BM;
    const int n0   = blockIdx.x * BN;
    const int wid  = t >> 5;
    const int lane = t & 31;
    const int gid  = lane >> 2;
    const int tid4 = lane & 3;
    const int wm   = (wid >> 2) * 64;
    const int wn   = (wid & 3) * 64;

    float acc[4][8][4];
#pragma unroll
    for (int i = 0; i < 4; i++)
#pragma unroll
        for (int j = 0; j < 8; j++)
#pragma unroll
            for (int r = 0; r < 4; r++) acc[i][j][r] = 0.f;

    auto load_stage = [&](int s, int k0) {
        uint32_t ab = smem_u32(Asm + s * A_STAGE);
        uint32_t bb = smem_u32(Bsm + s * B_STAGE);
#pragma unroll
        for (int j = 0; j < 4; j++) {               // A: 1024 float4
            int idx = j * 256 + t;
            int row = idx >> 3, c4 = (idx & 7) << 2;
            int gr = m0 + row;
            cp16(ab + (row * ASTR + c4) * 4,
                 A + (size_t)gr * FIN + k0 + c4, gr < NN ? 16 : 0);
        }
#pragma unroll
        for (int j = 0; j < 8; j++) {               // B: 2048 float4
            int idx = j * 256 + t;
            int row = idx >> 3, c4 = (idx & 7) << 2;
            cp16(bb + (row * ASTR + c4) * 4,
                 g_w1t + (size_t)(n0 + row) * FIN + k0 + c4, 16);
        }
        asm volatile("cp.async.commit_group;");
    };

    load_stage(0, 0);
    load_stage(1, BK2);

    const int NT = FIN / BK2;          // 128
    for (int kt = 0; kt < NT; kt++) {
        if (kt + 1 < NT) asm volatile("cp.async.wait_group 1;");
        else             asm volatile("cp.async.wait_group 0;");
        __syncthreads();
        const int s = kt % 3;
        const float* as = Asm + s * A_STAGE;
        const float* bs = Bsm + s * B_STAGE;

#pragma unroll
        for (int kk = 0; kk < BK2; kk += 8) {
            unsigned af[4][4], bf[8][2];
#pragma unroll
            for (int mt = 0; mt < 4; mt++) {
                int r = wm + mt * 16 + gid;
                af[mt][0] = tf32rna(as[r * ASTR + kk + tid4]);
                af[mt][1] = tf32rna(as[(r + 8) * ASTR + kk + tid4]);
                af[mt][2] = tf32rna(as[r * ASTR + kk + tid4 + 4]);
                af[mt][3] = tf32rna(as[(r + 8) * ASTR + kk + tid4 + 4]);
            }
#pragma unroll
            for (int nt = 0; nt < 8; nt++) {
                int c = wn + nt * 8 + gid;
                bf[nt][0] = __float_as_uint(bs[c * ASTR + kk + tid4]);
                bf[nt][1] = __float_as_uint(bs[c * ASTR + kk + tid4 + 4]);
            }
#pragma unroll
            for (int mt = 0; mt < 4; mt++)
#pragma unroll
                for (int nt = 0; nt < 8; nt++) {
                    asm volatile(
                        "mma.sync.aligned.m16n8k8.row.col.f32.tf32.tf32.f32 "
                        "{%0,%1,%2,%3}, {%4,%5,%6,%7}, {%8,%9}, {%0,%1,%2,%3};"
                        : "+f"(acc[mt][nt][0]), "+f"(acc[mt][nt][1]),
                          "+f"(acc[mt][nt][2]), "+f"(acc[mt][nt][3])
                        : "r"(af[mt][0]), "r"(af[mt][1]),
                          "r"(af[mt][2]), "r"(af[mt][3]),
                          "r"(bf[nt][0]), "r"(bf[nt][1]));
                }
        }
        if (kt + 2 < NT) load_stage((kt + 2) % 3, (kt + 2) * BK2);
    }

#pragma unroll
    for (int mt = 0; mt < 4; mt++) {
        int r1 = m0 + wm + mt * 16 + gid;
        int r2 = r1 + 8;
#pragma unroll
        for (int nt = 0; nt < 8; nt++) {
            int c = n0 + wn + nt * 8 + tid4 * 2;
            if (r1 < NN) *(float2*)(g_h1 + (size_t)r1 * HC + c) =
                make_float2(acc[mt][nt][0], acc[mt][nt][1]);
            if (r2 < NN) *(float2*)(g_h1 + (size_t)r2 * HC + c) =
                make_float2(acc[mt][nt][2], acc[mt][nt][3]);
        }
    }
}

// ---------------- per-node attention logits (layer 1) ------------------------
__global__ void alpha1_kernel(const float* __restrict__ asrc,
                              const float* __restrict__ adst) {
    int warp = (blockIdx.x * blockDim.x + threadIdx.x) >> 5;
    int lane = threadIdx.x & 31;
    if (warp >= NN) return;
    const float* row = g_h1 + (size_t)warp * HC;
    float ps[HEADS], pd[HEADS];
#pragma unroll
    for (int h = 0; h < HEADS; h++) { ps[h] = 0.f; pd[h] = 0.f; }
#pragma unroll
    for (int h = 0; h < HEADS; h++)
#pragma unroll
        for (int j = 0; j < 4; j++) {
            int idx = (h * 4 + j) * 32 + lane;
            float v = row[idx];
            ps[h] += v * asrc[idx];
            pd[h] += v * adst[idx];
        }
#pragma unroll
    for (int off = 16; off; off >>= 1)
#pragma unroll
        for (int h = 0; h < HEADS; h++) {
            ps[h] += __shfl_xor_sync(0xffffffffu, ps[h], off);
            pd[h] += __shfl_xor_sync(0xffffffffu, pd[h], off);
        }
    if (lane == 0)
#pragma unroll
        for (int h = 0; h < HEADS; h++) {
            g_as1[warp * HEADS + h] = ps[h];
            g_ad1[warp * HEADS + h] = pd[h];
        }
}

// ------------- fused layer-1 softmax + aggregate: warp per dst node ---------
__global__ __launch_bounds__(256) void fused_agg1() {
    int d    = (blockIdx.x * blockDim.x + threadIdx.x) >> 5;
    int lane = threadIdx.x & 31;
    if (d >= NN) return;
    const int beg = g_off[d], end = g_off[d + 1];
    const float4 ad = *(const float4*)(g_ad1 + d * 4);

    // pass 1: per-head max (lane-strided)
    float m0 = -1e30f, m1 = -1e30f, m2 = -1e30f, m3 = -1e30f;
    for (int i = beg + lane; i < end; i += 32) {
        int s = g_esrc[i];
        float4 as = *(const float4*)(g_as1 + s * 4);
        m0 = fmaxf(m0, lrelu(as.x + ad.x));
        m1 = fmaxf(m1, lrelu(as.y + ad.y));
        m2 = fmaxf(m2, lrelu(as.z + ad.z));
        m3 = fmaxf(m3, lrelu(as.w + ad.w));
    }
#pragma unroll
    for (int off = 16; off; off >>= 1) {
        m0 = fmaxf(m0, __shfl_xor_sync(0xffffffffu, m0, off));
        m1 = fmaxf(m1, __shfl_xor_sync(0xffffffffu, m1, off));
        m2 = fmaxf(m2, __shfl_xor_sync(0xffffffffu, m2, off));
        m3 = fmaxf(m3, __shfl_xor_sync(0xffffffffu, m3, off));
    }

    // pass 2 (merged): unnormalized accumulation + denominators
    float den0 = 0.f, den1 = 0.f, den2 = 0.f, den3 = 0.f;
    float4 a0 = {0,0,0,0}, a1 = {0,0,0,0}, a2 = {0,0,0,0}, a3 = {0,0,0,0};
    for (int i = beg; i < end; i++) {
        int s = g_esrc[i];
        float4 as = *(const float4*)(g_as1 + s * 4);
        float w0 = __expf(lrelu(as.x + ad.x) - m0); den0 += w0;
        float w1 = __expf(lrelu(as.y + ad.y) - m1); den1 += w1;
        float w2 = __expf(lrelu(as.z + ad.z) - m2); den2 += w2;
        float w3 = __expf(lrelu(as.w + ad.w) - m3); den3 += w3;
        const float4* row = (const float4*)(g_h1 + (size_t)s * HC);
        float4 v;
        v = row[lane];      a0.x += w0*v.x; a0.y += w0*v.y; a0.z += w0*v.z; a0.w += w0*v.w;
        v = row[32 + lane]; a1.x += w1*v.x; a1.y += w1*v.y; a1.z += w1*v.z; a1.w += w1*v.w;
        v = row[64 + lane]; a2.x += w2*v.x; a2.y += w2*v.y; a2.z += w2*v.z; a2.w += w2*v.w;
        v = row[96 + lane]; a3.x += w3*v.x; a3.y += w3*v.y; a3.z += w3*v.z; a3.w += w3*v.w;
    }
    const float r0 = 1.f / den0, r1 = 1.f / den1, r2 = 1.f / den2, r3 = 1.f / den3;
    a0.x *= r0; a0.y *= r0; a0.z *= r0; a0.w *= r0;
    a1.x *= r1; a1.y *= r1; a1.z *= r1; a1.w *= r1;
    a2.x *= r2; a2.y *= r2; a2.z *= r2; a2.w *= r2;
    a3.x *= r3; a3.y *= r3; a3.z *= r3; a3.w *= r3;

    float4* orow = (float4*)(g_out1 + (size_t)d * HC);
    orow[lane]      = a0;
    orow[32 + lane] = a1;
    orow[64 + lane] = a2;
    orow[96 + lane] = a3;
}

// --------- ELU + tiny GEMM2 (512x6) + layer-2 logits ------------------------
__global__ void elu_gemm2_kernel(const float* __restrict__ b1,
                                 const float* __restrict__ W2,
                                 const float* __restrict__ asrc2,
                                 const float* __restrict__ adst2) {
    int warp = (blockIdx.x * blockDim.x + threadIdx.x) >> 5;
    int lane = threadIdx.x & 31;
    if (warp >= NN) return;
    const float* row = g_out1 + (size_t)warp * HC;
    float acc[CLS];
#pragma unroll
    for (int c = 0; c < CLS; c++) acc[c] = 0.f;
#pragma unroll
    for (int i = 0; i < 16; i++) {
        int k = lane + 32 * i;
        float a = row[k] + b1[k];
        a = a > 0.f ? a : (__expf(a) - 1.f);
#pragma unroll
        for (int c = 0; c < CLS; c++) acc[c] += a * W2[k * CLS + c];
    }
#pragma unroll
    for (int off = 16; off; off >>= 1)
#pragma unroll
        for (int c = 0; c < CLS; c++)
            acc[c] += __shfl_xor_sync(0xffffffffu, acc[c], off);
    if (lane == 0) {
        float s2 = 0.f, d2 = 0.f;
#pragma unroll
        for (int c = 0; c < CLS; c++) {
            g_h2[warp * CLS + c] = acc[c];
            s2 += acc[c] * asrc2[c];
            d2 += acc[c] * adst2[c];
        }
        g_as2[warp] = s2;
        g_ad2[warp] = d2;
    }
}

// ------------- fused layer-2 softmax + aggregate ----------------------------
__global__ __launch_bounds__(256) void fused_agg2(const float* __restrict__ b2,
                                                  float* __restrict__ out) {
    int d    = (blockIdx.x * blockDim.x + threadIdx.x) >> 5;
    int lane = threadIdx.x & 31;
    if (d >= NN) return;
    const int beg = g_off[d], end = g_off[d + 1];
    const float ad = g_ad2[d];

    float m = -1e30f;
    for (int i = beg + lane; i < end; i += 32)
        m = fmaxf(m, lrelu(g_as2[g_esrc[i]] + ad));
#pragma unroll
    for (int off = 16; off; off >>= 1)
        m = fmaxf(m, __shfl_xor_sync(0xffffffffu, m, off));

    float den = 0.f;
    float acc[CLS];
#pragma unroll
    for (int c = 0; c < CLS; c++) acc[c] = 0.f;
    for (int i = beg + lane; i < end; i += 32) {
        int s = g_esrc[i];
        float w = __expf(lrelu(g_as2[s] + ad) - m);
        den += w;
#pragma unroll
        for (int c = 0; c < CLS; c++) acc[c] += w * g_h2[s * CLS + c];
    }
#pragma unroll
    for (int off = 16; off; off >>= 1) {
        den += __shfl_xor_sync(0xffffffffu, den, off);
#pragma unroll
        for (int c = 0; c < CLS; c++)
            acc[c] += __shfl_xor_sync(0xffffffffu, acc[c], off);
    }
    if (lane == 0) {
        float rden = 1.f / den;
#pragma unroll
        for (int c = 0; c < CLS; c++)
            out[d * CLS + c] = acc[c] * rden + b2[c];
    }
}

// ---------------- launch ----------------------------------------------------
extern "C" void kernel_launch(void* const* d_in, const int* in_sizes, int n_in,
                              void* d_out, int out_size) {
    const float* x     = (const float*)d_in[0];
    const int*   ei    = (const int*)d_in[1];
    const float* W1    = (const float*)d_in[2];
    const float* asrc1 = (const float*)d_in[3];
    const float* adst1 = (const float*)d_in[4];
    const float* b1    = (const float*)d_in[5];
    const float* W2    = (const float*)d_in[6];
    const float* asrc2 = (const float*)d_in[7];
    const float* adst2 = (const float*)d_in[8];
    const float* b2    = (const float*)d_in[9];
    float* out = (float*)d_out;

    cudaFuncSetAttribute(gemm1_tc,
                         cudaFuncAttributeMaxDynamicSharedMemorySize, SMEM_BYTES);

    zero_deg_kernel<<<(NN + 255) / 256, 256>>>();
    count_kernel<<<(ET + 255) / 256, 256>>>(ei);
    scan_kernel<<<1, 1024>>>();
    scatter_kernel<<<(ET + 255) / 256, 256>>>(ei);

    w1t_kernel<<<(FIN * HC + 255) / 256, 256>>>(W1);
    gemm1_tc<<<dim3(HC / BN, (NN + BM - 1) / BM), 256, SMEM_BYTES>>>(x);
    alpha1_kernel<<<(NN * 32 + 255) / 256, 256>>>(asrc1, adst1);
    fused_agg1<<<(NN * 32 + 255) / 256, 256>>>();
    elu_gemm2_kernel<<<(NN * 32 + 255) / 256, 256>>>(b1, W2, asrc2, adst2);
    fused_agg2<<<(NN * 32 + 255) / 256, 256>>>(b2, out);
}

// round 6
// speedup vs baseline: 3.7996x; 1.0555x over previous
#include <cuda_runtime.h>
#include <cuda_bf16.h>
#include <math.h>
#include <stdint.h>

#define NN 30000
#define EE 480000
#define ET (EE + NN)
#define FIN 4096
#define HC 512
#define HEADS 4
#define HID 128
#define CLS 6

// ---------------- scratch (static device globals) ---------------------------
__device__ float    g_h1[(size_t)NN * HC];
__device__ float    g_out1[(size_t)NN * HC];
__device__ float    g_w1t[(size_t)HC * FIN];   // W1^T, tf32-rounded, K-major
__device__ float    g_as1[NN * HEADS];
__device__ float    g_ad1[NN * HEADS];
__device__ float    g_h2[NN * CLS];
__device__ float    g_as2[NN];
__device__ float    g_ad2[NN];
__device__ int      g_deg[NN];
__device__ int      g_off[NN + 1];
__device__ int      g_pos[NN];
__device__ int      g_esrc[ET];

__device__ __forceinline__ float lrelu(float v) { return v > 0.f ? v : 0.2f * v; }
__device__ __forceinline__ unsigned tf32rna(float f) {
    unsigned u = __float_as_uint(f);
    asm("cvt.rna.tf32.f32 %0, %0;" : "+r"(u));
    return u;
}
__device__ __forceinline__ void edge_sd(const int* __restrict__ ei, int e,
                                        int& s, int& d) {
    if (e < EE) { s = ei[e]; d = ei[EE + e]; } else { s = d = e - EE; }
}
__device__ __forceinline__ uint32_t smem_u32(const void* p) {
    uint32_t a;
    asm("{ .reg .u64 t; cvta.to.shared.u64 t, %1; cvt.u32.u64 %0, t; }"
        : "=r"(a) : "l"(p));
    return a;
}
__device__ __forceinline__ void cp16(uint32_t saddr, const void* g, int bytes) {
    asm volatile("cp.async.ca.shared.global [%0], [%1], 16, %2;"
                 :: "r"(saddr), "l"(g), "r"(bytes));
}

// ---------------- CSR build --------------------------------------------------
__global__ void zero_deg_kernel() {
    int i = blockIdx.x * blockDim.x + threadIdx.x;
    if (i < NN) g_deg[i] = 0;
}
__global__ void count_kernel(const int* __restrict__ ei) {
    int e = blockIdx.x * blockDim.x + threadIdx.x;
    if (e >= ET) return;
    int s, d; edge_sd(ei, e, s, d);
    atomicAdd(&g_deg[d], 1);
}
__global__ void scan_kernel() {
    __shared__ int partial[1024];
    const int t = threadIdx.x;
    const int CH = (NN + 1023) / 1024;
    const int base = t * CH;
    int sum = 0;
    for (int c = 0; c < CH; c++) { int i = base + c; if (i < NN) sum += g_deg[i]; }
    partial[t] = sum;
    __syncthreads();
    for (int off = 1; off < 1024; off <<= 1) {
        int v = (t >= off) ? partial[t - off] : 0;
        __syncthreads();
        partial[t] += v;
        __syncthreads();
    }
    int acc = partial[t] - sum;
    for (int c = 0; c < CH; c++) {
        int i = base + c;
        if (i < NN) { g_off[i] = acc; g_pos[i] = acc; acc += g_deg[i]; }
    }
    if (t == 0) g_off[NN] = ET;
}
__global__ void scatter_kernel(const int* __restrict__ ei) {
    int e = blockIdx.x * blockDim.x + threadIdx.x;
    if (e >= ET) return;
    int s, d; edge_sd(ei, e, s, d);
    int p = atomicAdd(&g_pos[d], 1);
    g_esrc[p] = s;
}

// ---------------- transpose + tf32-round W1 ----------------------------------
__global__ void w1t_kernel(const float* __restrict__ W1) {
    int i = blockIdx.x * blockDim.x + threadIdx.x;
    if (i >= FIN * HC) return;
    int k = i / HC, n = i % HC;
    g_w1t[(size_t)n * FIN + k] = __uint_as_float(tf32rna(W1[i]));
}

// ---------------- GEMM1 (mma.sync tf32): h1 = x @ W1 ------------------------
#define BM 128
#define BN 256
#define BK2 32
#define ASTR 36
#define A_STAGE (BM * ASTR)
#define B_STAGE (BN * ASTR)
#define SMEM_BYTES (3 * (A_STAGE + B_STAGE) * 4)

__global__ __launch_bounds__(256, 1) void gemm1_tc(const float* __restrict__ A) {
    extern __shared__ float sm[];
    float* Asm = sm;
    float* Bsm = sm + 3 * A_STAGE;
    const int t    = threadIdx.x;
    const int m0   = blockIdx.y * BM;
    const int n0   = blockIdx.x * BN;
    const int wid  = t >> 5;
    const int lane = t & 31;
    const int gid  = lane >> 2;
    const int tid4 = lane & 3;
    const int wm   = (wid >> 2) * 64;
    const int wn   = (wid & 3) * 64;

    float acc[4][8][4];
#pragma unroll
    for (int i = 0; i < 4; i++)
#pragma unroll
        for (int j = 0; j < 8; j++)
#pragma unroll
            for (int r = 0; r < 4; r++) acc[i][j][r] = 0.f;

    auto load_stage = [&](int s, int k0) {
        uint32_t ab = smem_u32(Asm + s * A_STAGE);
        uint32_t bb = smem_u32(Bsm + s * B_STAGE);
#pragma unroll
        for (int j = 0; j < 4; j++) {
            int idx = j * 256 + t;
            int row = idx >> 3, c4 = (idx & 7) << 2;
            int gr = m0 + row;
            cp16(ab + (row * ASTR + c4) * 4,
                 A + (size_t)gr * FIN + k0 + c4, gr < NN ? 16 : 0);
        }
#pragma unroll
        for (int j = 0; j < 8; j++) {
            int idx = j * 256 + t;
            int row = idx >> 3, c4 = (idx & 7) << 2;
            cp16(bb + (row * ASTR + c4) * 4,
                 g_w1t + (size_t)(n0 + row) * FIN + k0 + c4, 16);
        }
        asm volatile("cp.async.commit_group;");
    };

    load_stage(0, 0);
    load_stage(1, BK2);

    const int NT = FIN / BK2;
    for (int kt = 0; kt < NT; kt++) {
        if (kt + 1 < NT) asm volatile("cp.async.wait_group 1;");
        else             asm volatile("cp.async.wait_group 0;");
        __syncthreads();
        const int s = kt % 3;
        const float* as = Asm + s * A_STAGE;
        const float* bs = Bsm + s * B_STAGE;

#pragma unroll
        for (int kk = 0; kk < BK2; kk += 8) {
            unsigned af[4][4], bf[8][2];
#pragma unroll
            for (int mt = 0; mt < 4; mt++) {
                int r = wm + mt * 16 + gid;
                af[mt][0] = tf32rna(as[r * ASTR + kk + tid4]);
                af[mt][1] = tf32rna(as[(r + 8) * ASTR + kk + tid4]);
                af[mt][2] = tf32rna(as[r * ASTR + kk + tid4 + 4]);
                af[mt][3] = tf32rna(as[(r + 8) * ASTR + kk + tid4 + 4]);
            }
#pragma unroll
            for (int nt = 0; nt < 8; nt++) {
                int c = wn + nt * 8 + gid;
                bf[nt][0] = __float_as_uint(bs[c * ASTR + kk + tid4]);
                bf[nt][1] = __float_as_uint(bs[c * ASTR + kk + tid4 + 4]);
            }
#pragma unroll
            for (int mt = 0; mt < 4; mt++)
#pragma unroll
                for (int nt = 0; nt < 8; nt++) {
                    asm volatile(
                        "mma.sync.aligned.m16n8k8.row.col.f32.tf32.tf32.f32 "
                        "{%0,%1,%2,%3}, {%4,%5,%6,%7}, {%8,%9}, {%0,%1,%2,%3};"
                        : "+f"(acc[mt][nt][0]), "+f"(acc[mt][nt][1]),
                          "+f"(acc[mt][nt][2]), "+f"(acc[mt][nt][3])
                        : "r"(af[mt][0]), "r"(af[mt][1]),
                          "r"(af[mt][2]), "r"(af[mt][3]),
                          "r"(bf[nt][0]), "r"(bf[nt][1]));
                }
        }
        if (kt + 2 < NT) load_stage((kt + 2) % 3, (kt + 2) * BK2);
    }

#pragma unroll
    for (int mt = 0; mt < 4; mt++) {
        int r1 = m0 + wm + mt * 16 + gid;
        int r2 = r1 + 8;
#pragma unroll
        for (int nt = 0; nt < 8; nt++) {
            int c = n0 + wn + nt * 8 + tid4 * 2;
            if (r1 < NN) *(float2*)(g_h1 + (size_t)r1 * HC + c) =
                make_float2(acc[mt][nt][0], acc[mt][nt][1]);
            if (r2 < NN) *(float2*)(g_h1 + (size_t)r2 * HC + c) =
                make_float2(acc[mt][nt][2], acc[mt][nt][3]);
        }
    }
}

// ---------------- per-node attention logits (layer 1) ------------------------
__global__ void alpha1_kernel(const float* __restrict__ asrc,
                              const float* __restrict__ adst) {
    int warp = (blockIdx.x * blockDim.x + threadIdx.x) >> 5;
    int lane = threadIdx.x & 31;
    if (warp >= NN) return;
    const float* row = g_h1 + (size_t)warp * HC;
    float ps[HEADS], pd[HEADS];
#pragma unroll
    for (int h = 0; h < HEADS; h++) { ps[h] = 0.f; pd[h] = 0.f; }
#pragma unroll
    for (int h = 0; h < HEADS; h++)
#pragma unroll
        for (int j = 0; j < 4; j++) {
            int idx = (h * 4 + j) * 32 + lane;
            float v = row[idx];
            ps[h] += v * asrc[idx];
            pd[h] += v * adst[idx];
        }
#pragma unroll
    for (int off = 16; off; off >>= 1)
#pragma unroll
        for (int h = 0; h < HEADS; h++) {
            ps[h] += __shfl_xor_sync(0xffffffffu, ps[h], off);
            pd[h] += __shfl_xor_sync(0xffffffffu, pd[h], off);
        }
    if (lane == 0)
#pragma unroll
        for (int h = 0; h < HEADS; h++) {
            g_as1[warp * HEADS + h] = ps[h];
            g_ad1[warp * HEADS + h] = pd[h];
        }
}

// ------- fused layer-1 softmax + aggregate: 4 warps per dst node (1 head) ---
__global__ __launch_bounds__(256) void fused_agg1() {
    int gw   = (blockIdx.x * blockDim.x + threadIdx.x) >> 5;
    int lane = threadIdx.x & 31;
    int d    = gw >> 2;
    int h    = gw & 3;
    if (d >= NN) return;
    const int beg = g_off[d], end = g_off[d + 1];
    const float ad = g_ad1[d * 4 + h];

    // pass 1: max (lane-strided)
    float m = -1e30f;
    for (int i = beg + lane; i < end; i += 32)
        m = fmaxf(m, lrelu(g_as1[g_esrc[i] * 4 + h] + ad));
#pragma unroll
    for (int off = 16; off; off >>= 1)
        m = fmaxf(m, __shfl_xor_sync(0xffffffffu, m, off));

    // pass 2 (merged): unnormalized accumulation + denominator
    float den = 0.f;
    float4 a = {0.f, 0.f, 0.f, 0.f};
    const float4* hbase = (const float4*)g_h1;
    for (int i = beg; i < end; i++) {
        int s = g_esrc[i];                               // broadcast
        float w = __expf(lrelu(g_as1[s * 4 + h] + ad) - m);
        den += w;
        float4 v = hbase[(size_t)s * 128 + h * 32 + lane];
        a.x += w * v.x; a.y += w * v.y; a.z += w * v.z; a.w += w * v.w;
    }
    const float r = 1.f / den;
    a.x *= r; a.y *= r; a.z *= r; a.w *= r;
    ((float4*)g_out1)[(size_t)d * 128 + h * 32 + lane] = a;
}

// --------- ELU + tiny GEMM2 (512x6) + layer-2 logits ------------------------
__global__ void elu_gemm2_kernel(const float* __restrict__ b1,
                                 const float* __restrict__ W2,
                                 const float* __restrict__ asrc2,
                                 const float* __restrict__ adst2) {
    int warp = (blockIdx.x * blockDim.x + threadIdx.x) >> 5;
    int lane = threadIdx.x & 31;
    if (warp >= NN) return;
    const float* row = g_out1 + (size_t)warp * HC;
    float acc[CLS];
#pragma unroll
    for (int c = 0; c < CLS; c++) acc[c] = 0.f;
#pragma unroll
    for (int i = 0; i < 16; i++) {
        int k = lane + 32 * i;
        float a = row[k] + b1[k];
        a = a > 0.f ? a : (__expf(a) - 1.f);
#pragma unroll
        for (int c = 0; c < CLS; c++) acc[c] += a * W2[k * CLS + c];
    }
#pragma unroll
    for (int off = 16; off; off >>= 1)
#pragma unroll
        for (int c = 0; c < CLS; c++)
            acc[c] += __shfl_xor_sync(0xffffffffu, acc[c], off);
    if (lane == 0) {
        float s2 = 0.f, d2 = 0.f;
#pragma unroll
        for (int c = 0; c < CLS; c++) {
            g_h2[warp * CLS + c] = acc[c];
            s2 += acc[c] * asrc2[c];
            d2 += acc[c] * adst2[c];
        }
        g_as2[warp] = s2;
        g_ad2[warp] = d2;
    }
}

// ------------- fused layer-2 softmax + aggregate ----------------------------
__global__ __launch_bounds__(256) void fused_agg2(const float* __restrict__ b2,
                                                  float* __restrict__ out) {
    int d    = (blockIdx.x * blockDim.x + threadIdx.x) >> 5;
    int lane = threadIdx.x & 31;
    if (d >= NN) return;
    const int beg = g_off[d], end = g_off[d + 1];
    const float ad = g_ad2[d];

    float m = -1e30f;
    for (int i = beg + lane; i < end; i += 32)
        m = fmaxf(m, lrelu(g_as2[g_esrc[i]] + ad));
#pragma unroll
    for (int off = 16; off; off >>= 1)
        m = fmaxf(m, __shfl_xor_sync(0xffffffffu, m, off));

    float den = 0.f;
    float acc[CLS];
#pragma unroll
    for (int c = 0; c < CLS; c++) acc[c] = 0.f;
    for (int i = beg + lane; i < end; i += 32) {
        int s = g_esrc[i];
        float w = __expf(lrelu(g_as2[s] + ad) - m);
        den += w;
#pragma unroll
        for (int c = 0; c < CLS; c++) acc[c] += w * g_h2[s * CLS + c];
    }
#pragma unroll
    for (int off = 16; off; off >>= 1) {
        den += __shfl_xor_sync(0xffffffffu, den, off);
#pragma unroll
        for (int c = 0; c < CLS; c++)
            acc[c] += __shfl_xor_sync(0xffffffffu, acc[c], off);
    }
    if (lane == 0) {
        float rden = 1.f / den;
#pragma unroll
        for (int c = 0; c < CLS; c++)
            out[d * CLS + c] = acc[c] * rden + b2[c];
    }
}

// ---------------- launch ----------------------------------------------------
extern "C" void kernel_launch(void* const* d_in, const int* in_sizes, int n_in,
                              void* d_out, int out_size) {
    const float* x     = (const float*)d_in[0];
    const int*   ei    = (const int*)d_in[1];
    const float* W1    = (const float*)d_in[2];
    const float* asrc1 = (const float*)d_in[3];
    const float* adst1 = (const float*)d_in[4];
    const float* b1    = (const float*)d_in[5];
    const float* W2    = (const float*)d_in[6];
    const float* asrc2 = (const float*)d_in[7];
    const float* adst2 = (const float*)d_in[8];
    const float* b2    = (const float*)d_in[9];
    float* out = (float*)d_out;

    static cudaStream_t s2 = nullptr;
    static cudaEvent_t  e1 = nullptr, e2 = nullptr;
    if (!s2) {
        cudaStreamCreateWithFlags(&s2, cudaStreamNonBlocking);
        cudaEventCreateWithFlags(&e1, cudaEventDisableTiming);
        cudaEventCreateWithFlags(&e2, cudaEventDisableTiming);
        cudaFuncSetAttribute(gemm1_tc,
                             cudaFuncAttributeMaxDynamicSharedMemorySize, SMEM_BYTES);
    }

    // fork: CSR build on side stream, overlapped with w1t + GEMM
    cudaEventRecord(e1, 0);
    cudaStreamWaitEvent(s2, e1, 0);
    zero_deg_kernel<<<(NN + 255) / 256, 256, 0, s2>>>();
    count_kernel<<<(ET + 255) / 256, 256, 0, s2>>>(ei);
    scan_kernel<<<1, 1024, 0, s2>>>();
    scatter_kernel<<<(ET + 255) / 256, 256, 0, s2>>>(ei);
    cudaEventRecord(e2, s2);

    w1t_kernel<<<(FIN * HC + 255) / 256, 256>>>(W1);
    gemm1_tc<<<dim3(HC / BN, (NN + BM - 1) / BM), 256, SMEM_BYTES>>>(x);
    alpha1_kernel<<<(NN * 32 + 255) / 256, 256>>>(asrc1, adst1);

    // join: aggregation needs CSR + logits
    cudaStreamWaitEvent(0, e2, 0);
    fused_agg1<<<(NN * 128 + 255) / 256, 256>>>();
    elu_gemm2_kernel<<<(NN * 32 + 255) / 256, 256>>>(b1, W2, asrc2, adst2);
    fused_agg2<<<(NN * 32 + 255) / 256, 256>>>(b2, out);
}

// round 7
// speedup vs baseline: 3.8110x; 1.0030x over previous
#include <cuda_runtime.h>
#include <cuda_bf16.h>
#include <math.h>
#include <stdint.h>

#define NN 30000
#define EE 480000
#define ET (EE + NN)
#define FIN 4096
#define HC 512
#define HEADS 4
#define HID 128
#define CLS 6

// ---------------- scratch (static device globals) ---------------------------
__device__ float    g_h1[(size_t)NN * HC];
__device__ float    g_out1[(size_t)NN * HC];
__device__ float    g_w1t[(size_t)HC * FIN];   // W1^T, tf32-rounded, K-major
__device__ float    g_as1[NN * HEADS];
__device__ float    g_ad1[NN * HEADS];
__device__ float    g_h2[NN * CLS];
__device__ float    g_as2[NN];
__device__ float    g_ad2[NN];
__device__ int      g_deg[NN];
__device__ int      g_off[NN + 1];
__device__ int      g_pos[NN];
__device__ int      g_esrc[ET];

__device__ __forceinline__ float lrelu(float v) { return v > 0.f ? v : 0.2f * v; }
__device__ __forceinline__ unsigned tf32rna(float f) {
    unsigned u = __float_as_uint(f);
    asm("cvt.rna.tf32.f32 %0, %0;" : "+r"(u));
    return u;
}
__device__ __forceinline__ void edge_sd(const int* __restrict__ ei, int e,
                                        int& s, int& d) {
    if (e < EE) { s = ei[e]; d = ei[EE + e]; } else { s = d = e - EE; }
}
__device__ __forceinline__ uint32_t smem_u32(const void* p) {
    uint32_t a;
    asm("{ .reg .u64 t; cvta.to.shared.u64 t, %1; cvt.u32.u64 %0, t; }"
        : "=r"(a) : "l"(p));
    return a;
}
__device__ __forceinline__ void cp16(uint32_t saddr, const void* g, int bytes) {
    asm volatile("cp.async.ca.shared.global [%0], [%1], 16, %2;"
                 :: "r"(saddr), "l"(g), "r"(bytes));
}

// ---------------- CSR build --------------------------------------------------
__global__ void zero_deg_kernel() {
    int i = blockIdx.x * blockDim.x + threadIdx.x;
    if (i < NN) g_deg[i] = 0;
}
__global__ void count_kernel(const int* __restrict__ ei) {
    int e = blockIdx.x * blockDim.x + threadIdx.x;
    if (e >= ET) return;
    int s, d; edge_sd(ei, e, s, d);
    atomicAdd(&g_deg[d], 1);
}
__global__ void scan_kernel() {
    __shared__ int partial[1024];
    const int t = threadIdx.x;
    const int CH = (NN + 1023) / 1024;
    const int base = t * CH;
    int sum = 0;
    for (int c = 0; c < CH; c++) { int i = base + c; if (i < NN) sum += g_deg[i]; }
    partial[t] = sum;
    __syncthreads();
    for (int off = 1; off < 1024; off <<= 1) {
        int v = (t >= off) ? partial[t - off] : 0;
        __syncthreads();
        partial[t] += v;
        __syncthreads();
    }
    int acc = partial[t] - sum;
    for (int c = 0; c < CH; c++) {
        int i = base + c;
        if (i < NN) { g_off[i] = acc; g_pos[i] = acc; acc += g_deg[i]; }
    }
    if (t == 0) g_off[NN] = ET;
}
__global__ void scatter_kernel(const int* __restrict__ ei) {
    int e = blockIdx.x * blockDim.x + threadIdx.x;
    if (e >= ET) return;
    int s, d; edge_sd(ei, e, s, d);
    int p = atomicAdd(&g_pos[d], 1);
    g_esrc[p] = s;
}

// ---------- transpose + tf32-round W1 (32x32 shared tiles, coalesced) -------
__global__ __launch_bounds__(256) void w1t_kernel(const float* __restrict__ W1) {
    __shared__ float tile[32][33];
    const int k0 = blockIdx.y * 32;         // FIN / 32 = 128
    const int n0 = blockIdx.x * 32;         // HC / 32 = 16
    const int tx = threadIdx.x & 31;
    const int ty = threadIdx.x >> 5;        // 0..7
#pragma unroll
    for (int r = 0; r < 4; r++) {
        int k = k0 + ty + r * 8;
        tile[ty + r * 8][tx] = __uint_as_float(tf32rna(W1[(size_t)k * HC + n0 + tx]));
    }
    __syncthreads();
#pragma unroll
    for (int r = 0; r < 4; r++) {
        int n = n0 + ty + r * 8;
        g_w1t[(size_t)n * FIN + k0 + tx] = tile[tx][ty + r * 8];
    }
}

// ---------------- GEMM1 (mma.sync tf32): h1 = x @ W1 ------------------------
#define BM 128
#define BN 256
#define BK2 32
#define ASTR 36
#define A_STAGE (BM * ASTR)
#define B_STAGE (BN * ASTR)
#define SMEM_BYTES (3 * (A_STAGE + B_STAGE) * 4)

__global__ __launch_bounds__(256, 1) void gemm1_tc(const float* __restrict__ A) {
    extern __shared__ float sm[];
    float* Asm = sm;
    float* Bsm = sm + 3 * A_STAGE;
    const int t    = threadIdx.x;
    const int m0   = blockIdx.y * BM;
    const int n0   = blockIdx.x * BN;
    const int wid  = t >> 5;
    const int lane = t & 31;
    const int gid  = lane >> 2;
    const int tid4 = lane & 3;
    const int wm   = (wid >> 2) * 64;
    const int wn   = (wid & 3) * 64;

    float acc[4][8][4];
#pragma unroll
    for (int i = 0; i < 4; i++)
#pragma unroll
        for (int j = 0; j < 8; j++)
#pragma unroll
            for (int r = 0; r < 4; r++) acc[i][j][r] = 0.f;

    auto load_stage = [&](int s, int k0) {
        uint32_t ab = smem_u32(Asm + s * A_STAGE);
        uint32_t bb = smem_u32(Bsm + s * B_STAGE);
#pragma unroll
        for (int j = 0; j < 4; j++) {
            int idx = j * 256 + t;
            int row = idx >> 3, c4 = (idx & 7) << 2;
            int gr = m0 + row;
            cp16(ab + (row * ASTR + c4) * 4,
                 A + (size_t)gr * FIN + k0 + c4, gr < NN ? 16 : 0);
        }
#pragma unroll
        for (int j = 0; j < 8; j++) {
            int idx = j * 256 + t;
            int row = idx >> 3, c4 = (idx & 7) << 2;
            cp16(bb + (row * ASTR + c4) * 4,
                 g_w1t + (size_t)(n0 + row) * FIN + k0 + c4, 16);
        }
        asm volatile("cp.async.commit_group;");
    };

    load_stage(0, 0);
    load_stage(1, BK2);

    const int NT = FIN / BK2;
    for (int kt = 0; kt < NT; kt++) {
        if (kt + 1 < NT) asm volatile("cp.async.wait_group 1;");
        else             asm volatile("cp.async.wait_group 0;");
        __syncthreads();
        const int s = kt % 3;
        const float* as = Asm + s * A_STAGE;
        const float* bs = Bsm + s * B_STAGE;

#pragma unroll
        for (int kk = 0; kk < BK2; kk += 8) {
            unsigned af[4][4], bf[8][2];
#pragma unroll
            for (int mt = 0; mt < 4; mt++) {
                int r = wm + mt * 16 + gid;
                af[mt][0] = tf32rna(as[r * ASTR + kk + tid4]);
                af[mt][1] = tf32rna(as[(r + 8) * ASTR + kk + tid4]);
                af[mt][2] = tf32rna(as[r * ASTR + kk + tid4 + 4]);
                af[mt][3] = tf32rna(as[(r + 8) * ASTR + kk + tid4 + 4]);
            }
#pragma unroll
            for (int nt = 0; nt < 8; nt++) {
                int c = wn + nt * 8 + gid;
                bf[nt][0] = __float_as_uint(bs[c * ASTR + kk + tid4]);
                bf[nt][1] = __float_as_uint(bs[c * ASTR + kk + tid4 + 4]);
            }
#pragma unroll
            for (int mt = 0; mt < 4; mt++)
#pragma unroll
                for (int nt = 0; nt < 8; nt++) {
                    asm volatile(
                        "mma.sync.aligned.m16n8k8.row.col.f32.tf32.tf32.f32 "
                        "{%0,%1,%2,%3}, {%4,%5,%6,%7}, {%8,%9}, {%0,%1,%2,%3};"
                        : "+f"(acc[mt][nt][0]), "+f"(acc[mt][nt][1]),
                          "+f"(acc[mt][nt][2]), "+f"(acc[mt][nt][3])
                        : "r"(af[mt][0]), "r"(af[mt][1]),
                          "r"(af[mt][2]), "r"(af[mt][3]),
                          "r"(bf[nt][0]), "r"(bf[nt][1]));
                }
        }
        if (kt + 2 < NT) load_stage((kt + 2) % 3, (kt + 2) * BK2);
    }

#pragma unroll
    for (int mt = 0; mt < 4; mt++) {
        int r1 = m0 + wm + mt * 16 + gid;
        int r2 = r1 + 8;
#pragma unroll
        for (int nt = 0; nt < 8; nt++) {
            int c = n0 + wn + nt * 8 + tid4 * 2;
            if (r1 < NN) *(float2*)(g_h1 + (size_t)r1 * HC + c) =
                make_float2(acc[mt][nt][0], acc[mt][nt][1]);
            if (r2 < NN) *(float2*)(g_h1 + (size_t)r2 * HC + c) =
                make_float2(acc[mt][nt][2], acc[mt][nt][3]);
        }
    }
}

// ---------------- per-node attention logits (layer 1) ------------------------
__global__ void alpha1_kernel(const float* __restrict__ asrc,
                              const float* __restrict__ adst) {
    int warp = (blockIdx.x * blockDim.x + threadIdx.x) >> 5;
    int lane = threadIdx.x & 31;
    if (warp >= NN) return;
    const float* row = g_h1 + (size_t)warp * HC;
    float ps[HEADS], pd[HEADS];
#pragma unroll
    for (int h = 0; h < HEADS; h++) { ps[h] = 0.f; pd[h] = 0.f; }
#pragma unroll
    for (int h = 0; h < HEADS; h++)
#pragma unroll
        for (int j = 0; j < 4; j++) {
            int idx = (h * 4 + j) * 32 + lane;
            float v = row[idx];
            ps[h] += v * asrc[idx];
            pd[h] += v * adst[idx];
        }
#pragma unroll
    for (int off = 16; off; off >>= 1)
#pragma unroll
        for (int h = 0; h < HEADS; h++) {
            ps[h] += __shfl_xor_sync(0xffffffffu, ps[h], off);
            pd[h] += __shfl_xor_sync(0xffffffffu, pd[h], off);
        }
    if (lane == 0)
#pragma unroll
        for (int h = 0; h < HEADS; h++) {
            g_as1[warp * HEADS + h] = ps[h];
            g_ad1[warp * HEADS + h] = pd[h];
        }
}

// ------- fused layer-1 softmax + aggregate: 4 warps per dst node (1 head) ---
// Fast path for deg<=32 (>99.9% of nodes): lane-parallel logits, one pass.
__global__ __launch_bounds__(256) void fused_agg1() {
    int gw   = (blockIdx.x * blockDim.x + threadIdx.x) >> 5;
    int lane = threadIdx.x & 31;
    int d    = gw >> 2;
    int h    = gw & 3;
    if (d >= NN) return;
    const int beg = g_off[d], end = g_off[d + 1];
    const int deg = end - beg;
    const float ad = g_ad1[d * 4 + h];
    const float4* hbase = (const float4*)g_h1;

    float den;
    float4 a = {0.f, 0.f, 0.f, 0.f};

    if (deg <= 32) {
        int   s_l = (lane < deg) ? g_esrc[beg + lane] : 0;
        float e_l = (lane < deg) ? lrelu(g_as1[s_l * 4 + h] + ad) : -1e30f;
        float m = e_l;
#pragma unroll
        for (int off = 16; off; off >>= 1)
            m = fmaxf(m, __shfl_xor_sync(0xffffffffu, m, off));
        float w_l = (lane < deg) ? __expf(e_l - m) : 0.f;
        den = w_l;
#pragma unroll
        for (int off = 16; off; off >>= 1)
            den += __shfl_xor_sync(0xffffffffu, den, off);
#pragma unroll 8
        for (int j = 0; j < deg; j++) {
            float w = __shfl_sync(0xffffffffu, w_l, j);
            int   s = __shfl_sync(0xffffffffu, s_l, j);
            float4 v = hbase[(size_t)s * 128 + h * 32 + lane];
            a.x += w * v.x; a.y += w * v.y; a.z += w * v.z; a.w += w * v.w;
        }
    } else {
        // general path: two passes, chunked lane-parallel
        float m = -1e30f;
        for (int i = beg + lane; i < end; i += 32)
            m = fmaxf(m, lrelu(g_as1[g_esrc[i] * 4 + h] + ad));
#pragma unroll
        for (int off = 16; off; off >>= 1)
            m = fmaxf(m, __shfl_xor_sync(0xffffffffu, m, off));
        den = 0.f;
        for (int base = beg; base < end; base += 32) {
            int   idx = base + lane;
            int   s_l = (idx < end) ? g_esrc[idx] : 0;
            float w_l = (idx < end)
                      ? __expf(lrelu(g_as1[s_l * 4 + h] + ad) - m) : 0.f;
            den += w_l;
            int n = min(32, end - base);
#pragma unroll 8
            for (int j = 0; j < n; j++) {
                float w = __shfl_sync(0xffffffffu, w_l, j);
                int   s = __shfl_sync(0xffffffffu, s_l, j);
                float4 v = hbase[(size_t)s * 128 + h * 32 + lane];
                a.x += w * v.x; a.y += w * v.y; a.z += w * v.z; a.w += w * v.w;
            }
        }
#pragma unroll
        for (int off = 16; off; off >>= 1)
            den += __shfl_xor_sync(0xffffffffu, den, off);
    }
    const float r = 1.f / den;
    a.x *= r; a.y *= r; a.z *= r; a.w *= r;
    ((float4*)g_out1)[(size_t)d * 128 + h * 32 + lane] = a;
}

// --------- ELU + tiny GEMM2 (512x6) + layer-2 logits ------------------------
__global__ void elu_gemm2_kernel(const float* __restrict__ b1,
                                 const float* __restrict__ W2,
                                 const float* __restrict__ asrc2,
                                 const float* __restrict__ adst2) {
    int warp = (blockIdx.x * blockDim.x + threadIdx.x) >> 5;
    int lane = threadIdx.x & 31;
    if (warp >= NN) return;
    const float* row = g_out1 + (size_t)warp * HC;
    float acc[CLS];
#pragma unroll
    for (int c = 0; c < CLS; c++) acc[c] = 0.f;
#pragma unroll
    for (int i = 0; i < 16; i++) {
        int k = lane + 32 * i;
        float a = row[k] + b1[k];
        a = a > 0.f ? a : (__expf(a) - 1.f);
#pragma unroll
        for (int c = 0; c < CLS; c++) acc[c] += a * W2[k * CLS + c];
    }
#pragma unroll
    for (int off = 16; off; off >>= 1)
#pragma unroll
        for (int c = 0; c < CLS; c++)
            acc[c] += __shfl_xor_sync(0xffffffffu, acc[c], off);
    if (lane == 0) {
        float s2 = 0.f, d2 = 0.f;
#pragma unroll
        for (int c = 0; c < CLS; c++) {
            g_h2[warp * CLS + c] = acc[c];
            s2 += acc[c] * asrc2[c];
            d2 += acc[c] * adst2[c];
        }
        g_as2[warp] = s2;
        g_ad2[warp] = d2;
    }
}

// ------------- fused layer-2 softmax + aggregate ----------------------------
__global__ __launch_bounds__(256) void fused_agg2(const float* __restrict__ b2,
                                                  float* __restrict__ out) {
    int d    = (blockIdx.x * blockDim.x + threadIdx.x) >> 5;
    int lane = threadIdx.x & 31;
    if (d >= NN) return;
    const int beg = g_off[d], end = g_off[d + 1];
    const float ad = g_ad2[d];

    float m = -1e30f;
    for (int i = beg + lane; i < end; i += 32)
        m = fmaxf(m, lrelu(g_as2[g_esrc[i]] + ad));
#pragma unroll
    for (int off = 16; off; off >>= 1)
        m = fmaxf(m, __shfl_xor_sync(0xffffffffu, m, off));

    float den = 0.f;
    float acc[CLS];
#pragma unroll
    for (int c = 0; c < CLS; c++) acc[c] = 0.f;
    for (int i = beg + lane; i < end; i += 32) {
        int s = g_esrc[i];
        float w = __expf(lrelu(g_as2[s] + ad) - m);
        den += w;
#pragma unroll
        for (int c = 0; c < CLS; c++) acc[c] += w * g_h2[s * CLS + c];
    }
#pragma unroll
    for (int off = 16; off; off >>= 1) {
        den += __shfl_xor_sync(0xffffffffu, den, off);
#pragma unroll
        for (int c = 0; c < CLS; c++)
            acc[c] += __shfl_xor_sync(0xffffffffu, acc[c], off);
    }
    if (lane == 0) {
        float rden = 1.f / den;
#pragma unroll
        for (int c = 0; c < CLS; c++)
            out[d * CLS + c] = acc[c] * rden + b2[c];
    }
}

// ---------------- launch ----------------------------------------------------
extern "C" void kernel_launch(void* const* d_in, const int* in_sizes, int n_in,
                              void* d_out, int out_size) {
    const float* x     = (const float*)d_in[0];
    const int*   ei    = (const int*)d_in[1];
    const float* W1    = (const float*)d_in[2];
    const float* asrc1 = (const float*)d_in[3];
    const float* adst1 = (const float*)d_in[4];
    const float* b1    = (const float*)d_in[5];
    const float* W2    = (const float*)d_in[6];
    const float* asrc2 = (const float*)d_in[7];
    const float* adst2 = (const float*)d_in[8];
    const float* b2    = (const float*)d_in[9];
    float* out = (float*)d_out;

    static cudaStream_t s2 = nullptr;
    static cudaEvent_t  e1 = nullptr, e2 = nullptr;
    if (!s2) {
        cudaStreamCreateWithFlags(&s2, cudaStreamNonBlocking);
        cudaEventCreateWithFlags(&e1, cudaEventDisableTiming);
        cudaEventCreateWithFlags(&e2, cudaEventDisableTiming);
        cudaFuncSetAttribute(gemm1_tc,
                             cudaFuncAttributeMaxDynamicSharedMemorySize, SMEM_BYTES);
    }

    // fork: CSR build on side stream, overlapped with w1t + GEMM
    cudaEventRecord(e1, 0);
    cudaStreamWaitEvent(s2, e1, 0);
    zero_deg_kernel<<<(NN + 255) / 256, 256, 0, s2>>>();
    count_kernel<<<(ET + 255) / 256, 256, 0, s2>>>(ei);
    scan_kernel<<<1, 1024, 0, s2>>>();
    scatter_kernel<<<(ET + 255) / 256, 256, 0, s2>>>(ei);
    cudaEventRecord(e2, s2);

    w1t_kernel<<<dim3(HC / 32, FIN / 32), 256>>>(W1);
    gemm1_tc<<<dim3(HC / BN, (NN + BM - 1) / BM), 256, SMEM_BYTES>>>(x);
    alpha1_kernel<<<(NN * 32 + 255) / 256, 256>>>(asrc1, adst1);

    // join: aggregation needs CSR + logits
    cudaStreamWaitEvent(0, e2, 0);
    fused_agg1<<<(NN * 128 + 255) / 256, 256>>>();
    elu_gemm2_kernel<<<(NN * 32 + 255) / 256, 256>>>(b1, W2, asrc2, adst2);
    fused_agg2<<<(NN * 32 + 255) / 256, 256>>>(b2, out);
}